// round 2
// baseline (speedup 1.0000x reference)
#include <cuda_runtime.h>
#include <cstdint>

// ---------------------------------------------------------------------------
// RelationNetwork fused pipeline v2, fp32 packed f32x2 FMA (sm_103a).
// K1: roi @ [q_w;k_w;out_w]^T -> g_qkp (64x128 tiles, dup-A smem)
// K2: aff = 0.125 * Q K^T       (128x128 tiles, dup-A smem)
// K3: fused pos-proj + log + add + softmax (prefetch depth 4)
// K4: out = soft @ P (split-K x4 into scratch) ; K5: reduce + bias
// ---------------------------------------------------------------------------

__device__ float g_qkp [3u * 16u * 1024u * 64u];   // 12 MB  [seg][g][row][64]
__device__ float g_aff [1024u * 16u * 1024u];      // 64 MB  [n][g][m]; reused as K4 scratch
__device__ float g_soft[16u * 1024u * 1024u];      // 64 MB  [g][n][m]

// ---- packed f32x2 helpers --------------------------------------------------
__device__ __forceinline__ unsigned long long pack2(float a, float b) {
    unsigned long long r;
    asm("mov.b64 %0, {%1, %2};" : "=l"(r)
        : "r"(__float_as_uint(a)), "r"(__float_as_uint(b)));
    return r;
}
__device__ __forceinline__ void unpack2(unsigned long long v, float& a, float& b) {
    unsigned int lo, hi;
    asm("mov.b64 {%0, %1}, %2;" : "=r"(lo), "=r"(hi) : "l"(v));
    a = __uint_as_float(lo);
    b = __uint_as_float(hi);
}
__device__ __forceinline__ unsigned long long fma2(unsigned long long a,
                                                   unsigned long long b,
                                                   unsigned long long c) {
    unsigned long long d;
    asm("fma.rn.f32x2 %0, %1, %2, %3;" : "=l"(d) : "l"(a), "l"(b), "l"(c));
    return d;
}

// ---------------------------------------------------------------------------
// K1: 1024x3072x1024 NT GEMM. 64x128 tiles, 256 threads, 4x8 per thread.
// A stored in smem as duplicated (a,a) u64 pairs -> no per-FMA packing.
// ---------------------------------------------------------------------------
__global__ __launch_bounds__(256) void k1_qkp(
    const float* __restrict__ A,
    const float* __restrict__ qw, const float* __restrict__ kw,
    const float* __restrict__ ow,
    const float* __restrict__ qb, const float* __restrict__ kb)
{
    __shared__ unsigned long long As2[16][66];   // [k][n] dup pairs
    __shared__ float Bs[16][132];                // [k][c]
    const int tid  = threadIdx.x;
    const int col0 = blockIdx.x << 7;            // 0..2944
    const int row0 = blockIdx.y << 6;            // 0..960
    const int seg  = col0 >> 10;
    const float* B = (seg == 0) ? qw : ((seg == 1) ? kw : ow);
    const int jb0  = col0 & 1023;

    const int ar = tid >> 2;          // 0..63
    const int ak = (tid & 3) << 2;    // 0,4,8,12
    const int tx = tid & 15;          // c-group
    const int ty = tid >> 4;          // n-group (0..15)

    unsigned long long acc[4][4];
#pragma unroll
    for (int i = 0; i < 4; i++)
#pragma unroll
        for (int j = 0; j < 4; j++) acc[i][j] = 0ULL;

    const float* Ar  = A + (row0 + ar) * 1024 + ak;
    const float* Br0 = B + (jb0 + ar) * 1024 + ak;
    const float* Br1 = Br0 + 64 * 1024;

#pragma unroll 1
    for (int kt = 0; kt < 1024; kt += 16) {
        float4 a0 = *(const float4*)(Ar + kt);
        float4 b0 = *(const float4*)(Br0 + kt);
        float4 b1 = *(const float4*)(Br1 + kt);
        __syncthreads();
        As2[ak + 0][ar] = pack2(a0.x, a0.x);
        As2[ak + 1][ar] = pack2(a0.y, a0.y);
        As2[ak + 2][ar] = pack2(a0.z, a0.z);
        As2[ak + 3][ar] = pack2(a0.w, a0.w);
        Bs[ak + 0][ar] = b0.x; Bs[ak + 1][ar] = b0.y;
        Bs[ak + 2][ar] = b0.z; Bs[ak + 3][ar] = b0.w;
        Bs[ak + 0][ar + 64] = b1.x; Bs[ak + 1][ar + 64] = b1.y;
        Bs[ak + 2][ar + 64] = b1.z; Bs[ak + 3][ar + 64] = b1.w;
        __syncthreads();
#pragma unroll
        for (int kk = 0; kk < 16; kk++) {
            const ulonglong2 ap0 = *(const ulonglong2*)&As2[kk][ty << 2];
            const ulonglong2 ap1 = *(const ulonglong2*)&As2[kk][(ty << 2) + 2];
            const ulonglong2 bv0 = *(const ulonglong2*)&Bs[kk][tx << 3];
            const ulonglong2 bv1 = *(const ulonglong2*)&Bs[kk][(tx << 3) + 4];
            const unsigned long long ad[4] = {ap0.x, ap0.y, ap1.x, ap1.y};
            const unsigned long long bp[4] = {bv0.x, bv0.y, bv1.x, bv1.y};
#pragma unroll
            for (int i = 0; i < 4; i++)
#pragma unroll
                for (int jp = 0; jp < 4; jp++)
                    acc[i][jp] = fma2(ad[i], bp[jp], acc[i][jp]);
        }
    }

    const int jl = jb0 + (tx << 3);
    float bias[8];
    if (seg == 0) {
        float4 t0 = *(const float4*)&qb[jl];
        float4 t1 = *(const float4*)&qb[jl + 4];
        bias[0] = t0.x; bias[1] = t0.y; bias[2] = t0.z; bias[3] = t0.w;
        bias[4] = t1.x; bias[5] = t1.y; bias[6] = t1.z; bias[7] = t1.w;
    } else if (seg == 1) {
        float4 t0 = *(const float4*)&kb[jl];
        float4 t1 = *(const float4*)&kb[jl + 4];
        bias[0] = t0.x; bias[1] = t0.y; bias[2] = t0.z; bias[3] = t0.w;
        bias[4] = t1.x; bias[5] = t1.y; bias[6] = t1.z; bias[7] = t1.w;
    } else {
#pragma unroll
        for (int j = 0; j < 8; j++) bias[j] = 0.0f;
    }
    const int g  = jl >> 6;
    const int d0 = jl & 63;
    float* ob = g_qkp + seg * (16 * 1024 * 64) + g * (1024 * 64) + d0;
#pragma unroll
    for (int i = 0; i < 4; i++) {
        const int n = row0 + (ty << 2) + i;
        float v[8];
#pragma unroll
        for (int jp = 0; jp < 4; jp++) {
            float x, y;
            unpack2(acc[i][jp], x, y);
            v[2 * jp]     = x + bias[2 * jp];
            v[2 * jp + 1] = y + bias[2 * jp + 1];
        }
        float4* dst = (float4*)(ob + n * 64);
        dst[0] = make_float4(v[0], v[1], v[2], v[3]);
        dst[1] = make_float4(v[4], v[5], v[6], v[7]);
    }
}

// ---------------------------------------------------------------------------
// K2: batched (16x) 1024x1024x64 NT GEMM: aff[n][g][m] = 0.125 * Q_g K_g^T
// 128x128 tiles, 256 threads, 8x8 per thread, dup-A smem.
// ---------------------------------------------------------------------------
__global__ __launch_bounds__(256) void k2_aff()
{
    __shared__ unsigned long long As2[16][132];
    __shared__ float Bs[16][132];
    const int tid = threadIdx.x;
    const int m0  = blockIdx.x << 7;
    const int n0  = blockIdx.y << 7;
    const int g   = blockIdx.z;
    const float* Q = g_qkp + g * (1024 * 64);
    const float* K = g_qkp + (16 + g) * (1024 * 64);

    const int lr = tid >> 2;
    const int lk = (tid & 3) << 2;
    const int tx = tid & 15;
    const int ty = tid >> 4;

    unsigned long long acc[8][4];
#pragma unroll
    for (int i = 0; i < 8; i++)
#pragma unroll
        for (int j = 0; j < 4; j++) acc[i][j] = 0ULL;

#pragma unroll 1
    for (int kt = 0; kt < 64; kt += 16) {
        float4 a0 = *(const float4*)&Q[(n0 + lr) * 64 + kt + lk];
        float4 a1 = *(const float4*)&Q[(n0 + lr + 64) * 64 + kt + lk];
        float4 b0 = *(const float4*)&K[(m0 + lr) * 64 + kt + lk];
        float4 b1 = *(const float4*)&K[(m0 + lr + 64) * 64 + kt + lk];
        __syncthreads();
        As2[lk + 0][lr] = pack2(a0.x, a0.x);
        As2[lk + 1][lr] = pack2(a0.y, a0.y);
        As2[lk + 2][lr] = pack2(a0.z, a0.z);
        As2[lk + 3][lr] = pack2(a0.w, a0.w);
        As2[lk + 0][lr + 64] = pack2(a1.x, a1.x);
        As2[lk + 1][lr + 64] = pack2(a1.y, a1.y);
        As2[lk + 2][lr + 64] = pack2(a1.z, a1.z);
        As2[lk + 3][lr + 64] = pack2(a1.w, a1.w);
        Bs[lk + 0][lr] = b0.x; Bs[lk + 1][lr] = b0.y;
        Bs[lk + 2][lr] = b0.z; Bs[lk + 3][lr] = b0.w;
        Bs[lk + 0][lr + 64] = b1.x; Bs[lk + 1][lr + 64] = b1.y;
        Bs[lk + 2][lr + 64] = b1.z; Bs[lk + 3][lr + 64] = b1.w;
        __syncthreads();
#pragma unroll
        for (int kk = 0; kk < 16; kk++) {
            const ulonglong2 ap0 = *(const ulonglong2*)&As2[kk][ty << 3];
            const ulonglong2 ap1 = *(const ulonglong2*)&As2[kk][(ty << 3) + 2];
            const ulonglong2 ap2 = *(const ulonglong2*)&As2[kk][(ty << 3) + 4];
            const ulonglong2 ap3 = *(const ulonglong2*)&As2[kk][(ty << 3) + 6];
            const ulonglong2 bv0 = *(const ulonglong2*)&Bs[kk][tx << 3];
            const ulonglong2 bv1 = *(const ulonglong2*)&Bs[kk][(tx << 3) + 4];
            const unsigned long long ad[8] = {ap0.x, ap0.y, ap1.x, ap1.y,
                                              ap2.x, ap2.y, ap3.x, ap3.y};
            const unsigned long long bp[4] = {bv0.x, bv0.y, bv1.x, bv1.y};
#pragma unroll
            for (int i = 0; i < 8; i++)
#pragma unroll
                for (int jp = 0; jp < 4; jp++)
                    acc[i][jp] = fma2(ad[i], bp[jp], acc[i][jp]);
        }
    }

    const int mc = m0 + (tx << 3);
#pragma unroll
    for (int i = 0; i < 8; i++) {
        const int n = n0 + (ty << 3) + i;
        float v[8];
#pragma unroll
        for (int jp = 0; jp < 4; jp++) {
            float x, y;
            unpack2(acc[i][jp], x, y);
            v[2 * jp]     = x * 0.125f;
            v[2 * jp + 1] = y * 0.125f;
        }
        float4* dst = (float4*)(g_aff + (n * 16 + g) * 1024 + mc);
        dst[0] = make_float4(v[0], v[1], v[2], v[3]);
        dst[1] = make_float4(v[4], v[5], v[6], v[7]);
    }
}

// ---------------------------------------------------------------------------
// K3: fused position projection + relu + log + add-aff + softmax.
// One block per n; prefetch depth 4 on the streamed 256MB pe read.
// ---------------------------------------------------------------------------
__global__ __launch_bounds__(256) void k3_softmax(
    const float* __restrict__ pe,    // [64][1024 n][1024 m]
    const float* __restrict__ pw,    // [16][64]
    const float* __restrict__ pb)    // [16]
{
    __shared__ unsigned long long swd[16 * 64];
    __shared__ float sb[16];
    __shared__ float red[16][8];
    const int n = blockIdx.x;
    const int t = threadIdx.x;

    for (int idx = t; idx < 1024; idx += 256) {
        const float w = pw[idx];
        swd[idx] = pack2(w, w);
    }
    if (t < 16) sb[t] = pb[t];
    __syncthreads();

    const int m0 = t << 2;
    unsigned long long acc[16][2];
#pragma unroll
    for (int gg = 0; gg < 16; gg++) { acc[gg][0] = 0ULL; acc[gg][1] = 0ULL; }

    const float* base = pe + (size_t)n * 1024 + m0;
    ulonglong2 cur[4];
#pragma unroll
    for (int j = 0; j < 4; j++)
        cur[j] = __ldg((const ulonglong2*)(base + (size_t)j * (1024 * 1024)));

#pragma unroll 1
    for (int e0 = 0; e0 < 64; e0 += 4) {
        ulonglong2 nxt[4];
        const int eb = (e0 + 4) & 63;   // wrap: final reload hits L2
#pragma unroll
        for (int j = 0; j < 4; j++)
            nxt[j] = __ldg((const ulonglong2*)(base + (size_t)(eb + j) * (1024 * 1024)));
#pragma unroll
        for (int j = 0; j < 4; j++) {
#pragma unroll
            for (int gg = 0; gg < 16; gg++) {
                const unsigned long long w = swd[(gg << 6) + e0 + j];
                acc[gg][0] = fma2(w, cur[j].x, acc[gg][0]);
                acc[gg][1] = fma2(w, cur[j].y, acc[gg][1]);
            }
        }
#pragma unroll
        for (int j = 0; j < 4; j++) cur[j] = nxt[j];
    }

    float wv[16][4];
    float mx[16];
#pragma unroll
    for (int gg = 0; gg < 16; gg++) {
        float x0, x1, x2, x3;
        unpack2(acc[gg][0], x0, x1);
        unpack2(acc[gg][1], x2, x3);
        const float bgg = sb[gg];
        const float4 av =
            *(const float4*)(g_aff + ((size_t)n * 16 + gg) * 1024 + m0);
        wv[gg][0] = __logf(fmaxf(x0 + bgg, 1e-6f)) + av.x;
        wv[gg][1] = __logf(fmaxf(x1 + bgg, 1e-6f)) + av.y;
        wv[gg][2] = __logf(fmaxf(x2 + bgg, 1e-6f)) + av.z;
        wv[gg][3] = __logf(fmaxf(x3 + bgg, 1e-6f)) + av.w;
        mx[gg] = fmaxf(fmaxf(wv[gg][0], wv[gg][1]),
                       fmaxf(wv[gg][2], wv[gg][3]));
    }

    const int lane = t & 31, wid = t >> 5;
#pragma unroll
    for (int gg = 0; gg < 16; gg++) {
        float m = mx[gg];
#pragma unroll
        for (int off = 16; off > 0; off >>= 1)
            m = fmaxf(m, __shfl_xor_sync(0xffffffffu, m, off));
        mx[gg] = m;
    }
    if (lane == 0) {
#pragma unroll
        for (int gg = 0; gg < 16; gg++) red[gg][wid] = mx[gg];
    }
    __syncthreads();
#pragma unroll
    for (int gg = 0; gg < 16; gg++) {
        float m = red[gg][0];
#pragma unroll
        for (int w = 1; w < 8; w++) m = fmaxf(m, red[gg][w]);
        mx[gg] = m;
    }
    __syncthreads();

    float sm[16];
#pragma unroll
    for (int gg = 0; gg < 16; gg++) {
        float s = 0.0f;
#pragma unroll
        for (int j = 0; j < 4; j++) {
            wv[gg][j] = __expf(wv[gg][j] - mx[gg]);
            s += wv[gg][j];
        }
#pragma unroll
        for (int off = 16; off > 0; off >>= 1)
            s += __shfl_xor_sync(0xffffffffu, s, off);
        sm[gg] = s;
    }
    if (lane == 0) {
#pragma unroll
        for (int gg = 0; gg < 16; gg++) red[gg][wid] = sm[gg];
    }
    __syncthreads();
#pragma unroll
    for (int gg = 0; gg < 16; gg++) {
        float s = red[gg][0];
#pragma unroll
        for (int w = 1; w < 8; w++) s += red[gg][w];
        const float inv = __fdividef(1.0f, s);
        const float4 o = make_float4(wv[gg][0] * inv, wv[gg][1] * inv,
                                     wv[gg][2] * inv, wv[gg][3] * inv);
        *(float4*)(g_soft + ((size_t)gg * 1024 + n) * 1024 + m0) = o;
    }
}

// ---------------------------------------------------------------------------
// K4: batched (16x) 1024x64x1024 NN GEMM with split-K x4.
// Partials into g_aff scratch (dead after K3). 64x64 tiles, 128 threads.
// ---------------------------------------------------------------------------
__global__ __launch_bounds__(128) void k4_out()
{
    __shared__ unsigned long long As2[16][66];   // dup soft pairs [k][n]
    __shared__ float Bs[16][68];                 // [k][o]
    const int tid = threadIdx.x;
    const int n0  = blockIdx.x << 6;
    const int g   = blockIdx.y;
    const int kc  = blockIdx.z;                  // 0..3, K chunk of 256
    const float* S = g_soft + (size_t)g * (1024 * 1024) + kc * 256;
    const float* P = g_qkp + (32 + g) * (1024 * 64) + kc * 256 * 64;

    const int tx = tid & 7;          // o groups of 8
    const int ty = tid >> 3;         // n groups of 4 (0..15)
    const int ar = tid >> 1;         // 0..63 (soft rows)
    const int ak = (tid & 1) << 3;   // 0 or 8
    const int br = tid >> 3;         // 0..15 (P rows)
    const int bc = (tid & 7) << 3;   // P cols

    unsigned long long acc[4][4];
#pragma unroll
    for (int i = 0; i < 4; i++)
#pragma unroll
        for (int j = 0; j < 4; j++) acc[i][j] = 0ULL;

#pragma unroll 1
    for (int kt = 0; kt < 256; kt += 16) {
        float4 a0 = *(const float4*)&S[(n0 + ar) * 1024 + kt + ak];
        float4 a1 = *(const float4*)&S[(n0 + ar) * 1024 + kt + ak + 4];
        float4 b0 = *(const float4*)&P[(kt + br) * 64 + bc];
        float4 b1 = *(const float4*)&P[(kt + br) * 64 + bc + 4];
        __syncthreads();
        As2[ak + 0][ar] = pack2(a0.x, a0.x);
        As2[ak + 1][ar] = pack2(a0.y, a0.y);
        As2[ak + 2][ar] = pack2(a0.z, a0.z);
        As2[ak + 3][ar] = pack2(a0.w, a0.w);
        As2[ak + 4][ar] = pack2(a1.x, a1.x);
        As2[ak + 5][ar] = pack2(a1.y, a1.y);
        As2[ak + 6][ar] = pack2(a1.z, a1.z);
        As2[ak + 7][ar] = pack2(a1.w, a1.w);
        *(float4*)&Bs[br][bc]     = b0;
        *(float4*)&Bs[br][bc + 4] = b1;
        __syncthreads();
#pragma unroll
        for (int kk = 0; kk < 16; kk++) {
            const ulonglong2 ap0 = *(const ulonglong2*)&As2[kk][ty << 2];
            const ulonglong2 ap1 = *(const ulonglong2*)&As2[kk][(ty << 2) + 2];
            const ulonglong2 bv0 = *(const ulonglong2*)&Bs[kk][tx << 3];
            const ulonglong2 bv1 = *(const ulonglong2*)&Bs[kk][(tx << 3) + 4];
            const unsigned long long ad[4] = {ap0.x, ap0.y, ap1.x, ap1.y};
            const unsigned long long bp[4] = {bv0.x, bv0.y, bv1.x, bv1.y};
#pragma unroll
            for (int i = 0; i < 4; i++)
#pragma unroll
                for (int jp = 0; jp < 4; jp++)
                    acc[i][jp] = fma2(ad[i], bp[jp], acc[i][jp]);
        }
    }

    const int o0 = tx << 3;
    float* part = g_aff + (size_t)kc * (1024 * 1024);
#pragma unroll
    for (int i = 0; i < 4; i++) {
        const int nn = n0 + (ty << 2) + i;
        float v[8];
#pragma unroll
        for (int jp = 0; jp < 4; jp++) {
            float x, y;
            unpack2(acc[i][jp], x, y);
            v[2 * jp]     = x;
            v[2 * jp + 1] = y;
        }
        float4* dst = (float4*)(part + nn * 1024 + (g << 6) + o0);
        dst[0] = make_float4(v[0], v[1], v[2], v[3]);
        dst[1] = make_float4(v[4], v[5], v[6], v[7]);
    }
}

// ---------------------------------------------------------------------------
// K5: reduce split-K partials + bias -> out
// ---------------------------------------------------------------------------
__global__ __launch_bounds__(256) void k5_reduce(float* __restrict__ out,
                                                 const float* __restrict__ obias)
{
    const int idx = (blockIdx.x << 8) + threadIdx.x;   // float4 index
    const size_t off = (size_t)idx << 2;
    float4 a = *(const float4*)(g_aff + off);
    float4 b = *(const float4*)(g_aff + off + (1u << 20));
    float4 c = *(const float4*)(g_aff + off + (2u << 20));
    float4 d = *(const float4*)(g_aff + off + (3u << 20));
    const float4 bb = *(const float4*)&obias[off & 1023];
    float4 r;
    r.x = a.x + b.x + c.x + d.x + bb.x;
    r.y = a.y + b.y + c.y + d.y + bb.y;
    r.z = a.z + b.z + c.z + d.z + bb.z;
    r.w = a.w + b.w + c.w + d.w + bb.w;
    *(float4*)(out + off) = r;
}

// ---------------------------------------------------------------------------
extern "C" void kernel_launch(void* const* d_in, const int* in_sizes, int n_in,
                              void* d_out, int out_size)
{
    const float* roi = (const float*)d_in[0];
    const float* pe  = (const float*)d_in[1];
    int ix = 2;
    if (ix < n_in && in_sizes[ix] == 1) ix++;   // skip nongt_dim scalar if present
    const float* pos_w = (const float*)d_in[ix++];
    const float* pos_b = (const float*)d_in[ix++];
    const float* q_w   = (const float*)d_in[ix++];
    const float* q_b   = (const float*)d_in[ix++];
    const float* k_w   = (const float*)d_in[ix++];
    const float* k_b   = (const float*)d_in[ix++];
    const float* out_w = (const float*)d_in[ix++];
    const float* out_b = (const float*)d_in[ix++];
    float* out = (float*)d_out;

    k1_qkp    <<<dim3(24, 16),    256>>>(roi, q_w, k_w, out_w, q_b, k_b);
    k2_aff    <<<dim3(8, 8, 16),  256>>>();
    k3_softmax<<<1024,            256>>>(pe, pos_w, pos_b);
    k4_out    <<<dim3(16, 16, 4), 128>>>();
    k5_reduce <<<1024,            256>>>(out, out_b);
}

// round 4
// speedup vs baseline: 1.6942x; 1.6942x over previous
#include <cuda_runtime.h>
#include <cuda_bf16.h>
#include <cstdint>

// ---------------------------------------------------------------------------
// RelationNetwork v4: K1 via mma.sync bf16 hi/lo split (portable tensor path;
// tcgen05 is rejected by the harness' sm_103 PTX target). Rest SIMT f32x2.
// k0: fp32 -> bf16 hi/lo split of [roi; q_w; k_w; out_w]
// K1: mma.sync 3-term split GEMM -> g_qkp fp32 (+q_b/k_b)
// K2: aff = 0.125 * Q K^T        (SIMT f32x2)
// K3: fused pos-proj + log + add + softmax (prefetch d4)
// K4: out = soft @ P, split-K x4 ; K5: reduce + bias
// ---------------------------------------------------------------------------

__device__ float g_qkp [3u * 16u * 1024u * 64u];         // 12 MB [seg][g][row][64]
__device__ float g_aff [1024u * 16u * 1024u];            // 64 MB [n][g][m]; K4 scratch
__device__ float g_soft[16u * 1024u * 1024u];            // 64 MB [g][n][m]
__device__ __nv_bfloat16 g_hi[4096u * 1024u];            // 8 MB  hi split
__device__ __nv_bfloat16 g_lo[4096u * 1024u];            // 8 MB  lo split

// ---- packed f32x2 helpers ---------------------------------------------------
__device__ __forceinline__ unsigned long long pack2(float a, float b) {
    unsigned long long r;
    asm("mov.b64 %0, {%1, %2};" : "=l"(r)
        : "r"(__float_as_uint(a)), "r"(__float_as_uint(b)));
    return r;
}
__device__ __forceinline__ void unpack2(unsigned long long v, float& a, float& b) {
    unsigned int lo, hi;
    asm("mov.b64 {%0, %1}, %2;" : "=r"(lo), "=r"(hi) : "l"(v));
    a = __uint_as_float(lo);
    b = __uint_as_float(hi);
}
__device__ __forceinline__ unsigned long long fma2(unsigned long long a,
                                                   unsigned long long b,
                                                   unsigned long long c) {
    unsigned long long d;
    asm("fma.rn.f32x2 %0, %1, %2, %3;" : "=l"(d) : "l"(a), "l"(b), "l"(c));
    return d;
}

// ---- mma.sync / cp.async helpers --------------------------------------------
__device__ __forceinline__ uint32_t smem_u32(const void* p) {
    uint32_t a;
    asm("{ .reg .u64 t; cvta.to.shared.u64 t, %1; cvt.u32.u64 %0, t; }"
        : "=r"(a) : "l"(p));
    return a;
}
#define CP16(s, g) \
    asm volatile("cp.async.cg.shared.global [%0], [%1], 16;" \
                 :: "r"(s), "l"(g) : "memory")
#define CP_COMMIT() asm volatile("cp.async.commit_group;" ::: "memory")
#define CP_WAIT(n)  asm volatile("cp.async.wait_group %0;" :: "n"(n) : "memory")
#define LDSM4(r, a) \
    asm volatile("ldmatrix.sync.aligned.m8n8.x4.shared.b16 {%0,%1,%2,%3}, [%4];" \
                 : "=r"((r)[0]), "=r"((r)[1]), "=r"((r)[2]), "=r"((r)[3]) \
                 : "r"(a))
#define MMA_BF16(d, a, b0, b1) \
    asm volatile("mma.sync.aligned.m16n8k16.row.col.f32.bf16.bf16.f32 " \
                 "{%0,%1,%2,%3}, {%4,%5,%6,%7}, {%8,%9}, {%0,%1,%2,%3};" \
                 : "+f"((d)[0]), "+f"((d)[1]), "+f"((d)[2]), "+f"((d)[3]) \
                 : "r"((a)[0]), "r"((a)[1]), "r"((a)[2]), "r"((a)[3]), \
                   "r"(b0), "r"(b1))

// smem swizzle: rows of 64B (32 bf16), 16B chunk c permuted by row.
// Conflict-free for both cp.async stores and 8-row ldmatrix phases.
__device__ __forceinline__ uint32_t swz(int r, int c) {
    return (uint32_t)(r * 64 + (((c ^ ((r >> 1) & 3)) & 3) << 4));
}

// ---------------------------------------------------------------------------
// k0: split [roi; q_w; k_w; out_w] (4 x 1024x1024 fp32) into bf16 hi + lo.
// ---------------------------------------------------------------------------
__global__ __launch_bounds__(256) void k0_convert(
    const float* __restrict__ roi, const float* __restrict__ qw,
    const float* __restrict__ kw,  const float* __restrict__ ow)
{
    const size_t e = ((size_t)blockIdx.x * 256 + threadIdx.x) * 4;
    const float* src;
    size_t off;
    if (e < (1u << 20))      { src = roi; off = e; }
    else if (e < (2u << 20)) { src = qw;  off = e - (1u << 20); }
    else if (e < (3u << 20)) { src = kw;  off = e - (2u << 20); }
    else                     { src = ow;  off = e - (3u << 20); }
    const float4 v = *(const float4*)(src + off);
    float x[4] = {v.x, v.y, v.z, v.w};
    __nv_bfloat16 h[4], l[4];
#pragma unroll
    for (int i = 0; i < 4; i++) {
        h[i] = __float2bfloat16(x[i]);
        l[i] = __float2bfloat16(x[i] - __bfloat162float(h[i]));
    }
    ((__nv_bfloat162*)(g_hi + e))[0] = __nv_bfloat162(h[0], h[1]);
    ((__nv_bfloat162*)(g_hi + e))[1] = __nv_bfloat162(h[2], h[3]);
    ((__nv_bfloat162*)(g_lo + e))[0] = __nv_bfloat162(l[0], l[1]);
    ((__nv_bfloat162*)(g_lo + e))[1] = __nv_bfloat162(l[2], l[3]);
}

// ---------------------------------------------------------------------------
// K1: C[1024,3072] = A[1024,1024] @ W[3072,1024]^T  via mma.sync bf16 split.
// 128x128 block tile, BK=32, 8 warps (2m x 4n) of 64x32, 2-stage cp.async.
// Stage layout (32KB): Ah[0] Al[8K] Bh[16K] Bl[24K], each 128 rows x 64B swz.
// ---------------------------------------------------------------------------
#define K1_STAGE 32768
#define K1_DSMEM (2 * K1_STAGE)

__device__ __forceinline__ void k1_issue(uint32_t so, int row0, int col0,
                                         int kc, int tid)
{
#pragma unroll
    for (int j = 0; j < 2; j++) {
        const int id = tid + (j << 8);
        const int r = id >> 2, c = id & 3;
        const uint32_t s = so + swz(r, c);
        const size_t goA = (size_t)(row0 + r) * 1024 + (kc << 5) + (c << 3);
        const size_t goB = (size_t)(1024 + col0 + r) * 1024 + (kc << 5) + (c << 3);
        CP16(s,         g_hi + goA);
        CP16(s +  8192, g_lo + goA);
        CP16(s + 16384, g_hi + goB);
        CP16(s + 24576, g_lo + goB);
    }
    CP_COMMIT();
}

__device__ __forceinline__ void k1_compute(uint32_t so, float acc[4][4][4],
                                           int wm, int wn, int lane)
{
    const int arow = lane & 15;
    const int achk = lane >> 4;
#pragma unroll
    for (int ks = 0; ks < 2; ks++) {
        uint32_t ah[4][4], al[4][4], bh[2][4], bl[2][4];
#pragma unroll
        for (int mi = 0; mi < 4; mi++) {
            const int r = wm * 64 + mi * 16 + arow;
            const uint32_t addr = so + swz(r, ks * 2 + achk);
            LDSM4(ah[mi], addr);
            LDSM4(al[mi], addr + 8192);
        }
#pragma unroll
        for (int nj = 0; nj < 2; nj++) {
            const int r = wn * 32 + nj * 16 + arow;
            const uint32_t addr = so + 16384 + swz(r, ks * 2 + achk);
            LDSM4(bh[nj], addr);
            LDSM4(bl[nj], addr + 8192);
        }
#pragma unroll
        for (int mi = 0; mi < 4; mi++)
#pragma unroll
            for (int n = 0; n < 4; n++) {
                const int nj = n >> 1, sb = n & 1;
                MMA_BF16(acc[mi][n], ah[mi], bh[nj][sb], bh[nj][sb + 2]);
                MMA_BF16(acc[mi][n], ah[mi], bl[nj][sb], bl[nj][sb + 2]);
                MMA_BF16(acc[mi][n], al[mi], bh[nj][sb], bh[nj][sb + 2]);
            }
    }
}

__global__ __launch_bounds__(256, 1) void k1_mma(
    const float* __restrict__ qb, const float* __restrict__ kb)
{
    extern __shared__ char sm1[];
    __shared__ float sbias[128];
    const uint32_t sbase = smem_u32(sm1);
    const int tid = threadIdx.x, lane = tid & 31, wid = tid >> 5;
    const int wm = wid >> 2, wn = wid & 3;
    const int col0 = blockIdx.x << 7, row0 = blockIdx.y << 7;
    const int seg = col0 >> 10, jb0 = col0 & 1023;

    if (tid < 128)
        sbias[tid] = (seg == 0) ? qb[jb0 + tid]
                   : ((seg == 1) ? kb[jb0 + tid] : 0.0f);

    float acc[4][4][4];
#pragma unroll
    for (int i = 0; i < 4; i++)
#pragma unroll
        for (int j = 0; j < 4; j++)
#pragma unroll
            for (int q = 0; q < 4; q++) acc[i][j][q] = 0.0f;

    k1_issue(sbase, row0, col0, 0, tid);

#pragma unroll 1
    for (int kc = 0; kc < 32; kc++) {
        const uint32_t so = sbase + ((kc & 1) ? (uint32_t)K1_STAGE : 0u);
        if (kc < 31) {
            k1_issue(sbase + (((kc + 1) & 1) ? (uint32_t)K1_STAGE : 0u),
                     row0, col0, kc + 1, tid);
            CP_WAIT(1);
        } else {
            CP_WAIT(0);
        }
        __syncthreads();
        k1_compute(so, acc, wm, wn, lane);
        __syncthreads();
    }

    // epilogue: scatter 2-float pairs with bias into g_qkp layout
#pragma unroll
    for (int mi = 0; mi < 4; mi++) {
        const int r0 = row0 + wm * 64 + mi * 16 + (lane >> 2);
#pragma unroll
        for (int n = 0; n < 4; n++) {
            const int lc = wn * 32 + n * 8 + ((lane & 3) << 1);
            const int jl = jb0 + lc;
            const int g = jl >> 6, d0 = jl & 63;
            const float b0 = sbias[lc], b1 = sbias[lc + 1];
            float* base = g_qkp + (size_t)seg * 1048576 + (size_t)g * 65536 + d0;
            *(float2*)(base + (size_t)r0 * 64) =
                make_float2(acc[mi][n][0] + b0, acc[mi][n][1] + b1);
            *(float2*)(base + (size_t)(r0 + 8) * 64) =
                make_float2(acc[mi][n][2] + b0, acc[mi][n][3] + b1);
        }
    }
}

// ---------------------------------------------------------------------------
// K2: batched (16x) 1024x1024x64 NT GEMM: aff[n][g][m] = 0.125 * Q_g K_g^T
// 128x128 tiles, 256 threads, 8x8 per thread, scalar-A + pack-per-use.
// ---------------------------------------------------------------------------
__global__ __launch_bounds__(256) void k2_aff()
{
    __shared__ float As[16][132];
    __shared__ float Bs[16][132];
    const int tid = threadIdx.x;
    const int m0  = blockIdx.x << 7;
    const int n0  = blockIdx.y << 7;
    const int g   = blockIdx.z;
    const float* Q = g_qkp + g * (1024 * 64);
    const float* K = g_qkp + (16 + g) * (1024 * 64);

    const int lr = tid >> 2;
    const int lk = (tid & 3) << 2;
    const int tx = tid & 15;
    const int ty = tid >> 4;

    unsigned long long acc[8][4];
#pragma unroll
    for (int i = 0; i < 8; i++)
#pragma unroll
        for (int j = 0; j < 4; j++) acc[i][j] = 0ULL;

#pragma unroll 1
    for (int kt = 0; kt < 64; kt += 16) {
        float4 a0 = *(const float4*)&Q[(n0 + lr) * 64 + kt + lk];
        float4 a1 = *(const float4*)&Q[(n0 + lr + 64) * 64 + kt + lk];
        float4 b0 = *(const float4*)&K[(m0 + lr) * 64 + kt + lk];
        float4 b1 = *(const float4*)&K[(m0 + lr + 64) * 64 + kt + lk];
        __syncthreads();
        As[lk + 0][lr] = a0.x; As[lk + 1][lr] = a0.y;
        As[lk + 2][lr] = a0.z; As[lk + 3][lr] = a0.w;
        As[lk + 0][lr + 64] = a1.x; As[lk + 1][lr + 64] = a1.y;
        As[lk + 2][lr + 64] = a1.z; As[lk + 3][lr + 64] = a1.w;
        Bs[lk + 0][lr] = b0.x; Bs[lk + 1][lr] = b0.y;
        Bs[lk + 2][lr] = b0.z; Bs[lk + 3][lr] = b0.w;
        Bs[lk + 0][lr + 64] = b1.x; Bs[lk + 1][lr + 64] = b1.y;
        Bs[lk + 2][lr + 64] = b1.z; Bs[lk + 3][lr + 64] = b1.w;
        __syncthreads();
#pragma unroll
        for (int kk = 0; kk < 16; kk++) {
            const float4 av0 = *(const float4*)&As[kk][ty << 3];
            const float4 av1 = *(const float4*)&As[kk][(ty << 3) + 4];
            const ulonglong2 bv0 = *(const ulonglong2*)&Bs[kk][tx << 3];
            const ulonglong2 bv1 = *(const ulonglong2*)&Bs[kk][(tx << 3) + 4];
            const float af[8] = {av0.x, av0.y, av0.z, av0.w,
                                 av1.x, av1.y, av1.z, av1.w};
            const unsigned long long bp[4] = {bv0.x, bv0.y, bv1.x, bv1.y};
#pragma unroll
            for (int i = 0; i < 8; i++) {
                const unsigned long long ad = pack2(af[i], af[i]);
#pragma unroll
                for (int jp = 0; jp < 4; jp++)
                    acc[i][jp] = fma2(ad, bp[jp], acc[i][jp]);
            }
        }
    }

    const int mc = m0 + (tx << 3);
#pragma unroll
    for (int i = 0; i < 8; i++) {
        const int n = n0 + (ty << 3) + i;
        float v[8];
#pragma unroll
        for (int jp = 0; jp < 4; jp++) {
            float x, y;
            unpack2(acc[i][jp], x, y);
            v[2 * jp]     = x * 0.125f;
            v[2 * jp + 1] = y * 0.125f;
        }
        float4* dst = (float4*)(g_aff + (n * 16 + g) * 1024 + mc);
        dst[0] = make_float4(v[0], v[1], v[2], v[3]);
        dst[1] = make_float4(v[4], v[5], v[6], v[7]);
    }
}

// ---------------------------------------------------------------------------
// K3: fused position projection + relu + log + add-aff + softmax.
// ---------------------------------------------------------------------------
__global__ __launch_bounds__(256) void k3_softmax(
    const float* __restrict__ pe,    // [64][1024 n][1024 m]
    const float* __restrict__ pw,    // [16][64]
    const float* __restrict__ pb)    // [16]
{
    __shared__ unsigned long long swd[16 * 64];
    __shared__ float sb[16];
    __shared__ float red[16][8];
    const int n = blockIdx.x;
    const int t = threadIdx.x;

    for (int idx = t; idx < 1024; idx += 256) {
        const float w = pw[idx];
        swd[idx] = pack2(w, w);
    }
    if (t < 16) sb[t] = pb[t];
    __syncthreads();

    const int m0 = t << 2;
    unsigned long long acc[16][2];
#pragma unroll
    for (int gg = 0; gg < 16; gg++) { acc[gg][0] = 0ULL; acc[gg][1] = 0ULL; }

    const float* base = pe + (size_t)n * 1024 + m0;
    ulonglong2 cur[4];
#pragma unroll
    for (int j = 0; j < 4; j++)
        cur[j] = __ldg((const ulonglong2*)(base + (size_t)j * (1024 * 1024)));

#pragma unroll 1
    for (int e0 = 0; e0 < 64; e0 += 4) {
        ulonglong2 nxt[4];
        const int eb = (e0 + 4) & 63;
#pragma unroll
        for (int j = 0; j < 4; j++)
            nxt[j] = __ldg((const ulonglong2*)(base + (size_t)(eb + j) * (1024 * 1024)));
#pragma unroll
        for (int j = 0; j < 4; j++) {
#pragma unroll
            for (int gg = 0; gg < 16; gg++) {
                const unsigned long long w = swd[(gg << 6) + e0 + j];
                acc[gg][0] = fma2(w, cur[j].x, acc[gg][0]);
                acc[gg][1] = fma2(w, cur[j].y, acc[gg][1]);
            }
        }
#pragma unroll
        for (int j = 0; j < 4; j++) cur[j] = nxt[j];
    }

    float wv[16][4];
    float mx[16];
#pragma unroll
    for (int gg = 0; gg < 16; gg++) {
        float x0, x1, x2, x3;
        unpack2(acc[gg][0], x0, x1);
        unpack2(acc[gg][1], x2, x3);
        const float bgg = sb[gg];
        const float4 av =
            *(const float4*)(g_aff + ((size_t)n * 16 + gg) * 1024 + m0);
        wv[gg][0] = __logf(fmaxf(x0 + bgg, 1e-6f)) + av.x;
        wv[gg][1] = __logf(fmaxf(x1 + bgg, 1e-6f)) + av.y;
        wv[gg][2] = __logf(fmaxf(x2 + bgg, 1e-6f)) + av.z;
        wv[gg][3] = __logf(fmaxf(x3 + bgg, 1e-6f)) + av.w;
        mx[gg] = fmaxf(fmaxf(wv[gg][0], wv[gg][1]),
                       fmaxf(wv[gg][2], wv[gg][3]));
    }

    const int lane = t & 31, wid = t >> 5;
#pragma unroll
    for (int gg = 0; gg < 16; gg++) {
        float m = mx[gg];
#pragma unroll
        for (int off = 16; off > 0; off >>= 1)
            m = fmaxf(m, __shfl_xor_sync(0xffffffffu, m, off));
        mx[gg] = m;
    }
    if (lane == 0) {
#pragma unroll
        for (int gg = 0; gg < 16; gg++) red[gg][wid] = mx[gg];
    }
    __syncthreads();
#pragma unroll
    for (int gg = 0; gg < 16; gg++) {
        float m = red[gg][0];
#pragma unroll
        for (int w = 1; w < 8; w++) m = fmaxf(m, red[gg][w]);
        mx[gg] = m;
    }
    __syncthreads();

    float sm[16];
#pragma unroll
    for (int gg = 0; gg < 16; gg++) {
        float s = 0.0f;
#pragma unroll
        for (int j = 0; j < 4; j++) {
            wv[gg][j] = __expf(wv[gg][j] - mx[gg]);
            s += wv[gg][j];
        }
#pragma unroll
        for (int off = 16; off > 0; off >>= 1)
            s += __shfl_xor_sync(0xffffffffu, s, off);
        sm[gg] = s;
    }
    if (lane == 0) {
#pragma unroll
        for (int gg = 0; gg < 16; gg++) red[gg][wid] = sm[gg];
    }
    __syncthreads();
#pragma unroll
    for (int gg = 0; gg < 16; gg++) {
        float s = red[gg][0];
#pragma unroll
        for (int w = 1; w < 8; w++) s += red[gg][w];
        const float inv = __fdividef(1.0f, s);
        const float4 o = make_float4(wv[gg][0] * inv, wv[gg][1] * inv,
                                     wv[gg][2] * inv, wv[gg][3] * inv);
        *(float4*)(g_soft + ((size_t)gg * 1024 + n) * 1024 + m0) = o;
    }
}

// ---------------------------------------------------------------------------
// K4: batched (16x) 1024x64x1024 NN GEMM, split-K x4.
// 128n x 64o tile, 128 threads, 8n x 8o per thread, scalar-A smem.
// ---------------------------------------------------------------------------
__global__ __launch_bounds__(128) void k4_out()
{
    __shared__ float As[16][132];   // [k][n] 128 rows
    __shared__ float Bs[16][68];    // [k][o]
    const int tid = threadIdx.x;
    const int n0  = blockIdx.x << 7;
    const int g   = blockIdx.y;
    const int kc  = blockIdx.z;
    const float* S = g_soft + (size_t)g * (1024 * 1024) + kc * 256;
    const float* P = g_qkp + (size_t)(32 + g) * 65536 + kc * 256 * 64;

    const int tx = tid & 7;          // o group of 8
    const int ty = tid >> 3;         // n group of 8 (0..15)

    unsigned long long acc[8][4];
#pragma unroll
    for (int i = 0; i < 8; i++)
#pragma unroll
        for (int j = 0; j < 4; j++) acc[i][j] = 0ULL;

#pragma unroll 1
    for (int kt = 0; kt < 256; kt += 16) {
        float4 a[4];
#pragma unroll
        for (int q = 0; q < 4; q++)
            a[q] = *(const float4*)&S[(size_t)(n0 + tid) * 1024 + kt + q * 4];
        const int r0 = tid >> 4, c0 = (tid & 15) << 2;
        float4 bA = *(const float4*)&P[(kt + r0) * 64 + c0];
        float4 bB = *(const float4*)&P[(kt + r0 + 8) * 64 + c0];
        __syncthreads();
#pragma unroll
        for (int q = 0; q < 4; q++) {
            As[q * 4 + 0][tid] = a[q].x;
            As[q * 4 + 1][tid] = a[q].y;
            As[q * 4 + 2][tid] = a[q].z;
            As[q * 4 + 3][tid] = a[q].w;
        }
        *(float4*)&Bs[r0][c0]     = bA;
        *(float4*)&Bs[r0 + 8][c0] = bB;
        __syncthreads();
#pragma unroll
        for (int kk = 0; kk < 16; kk++) {
            const float4 av0 = *(const float4*)&As[kk][ty << 3];
            const float4 av1 = *(const float4*)&As[kk][(ty << 3) + 4];
            const ulonglong2 bv0 = *(const ulonglong2*)&Bs[kk][tx << 3];
            const ulonglong2 bv1 = *(const ulonglong2*)&Bs[kk][(tx << 3) + 4];
            const float af[8] = {av0.x, av0.y, av0.z, av0.w,
                                 av1.x, av1.y, av1.z, av1.w};
            const unsigned long long bp[4] = {bv0.x, bv0.y, bv1.x, bv1.y};
#pragma unroll
            for (int i = 0; i < 8; i++) {
                const unsigned long long ad = pack2(af[i], af[i]);
#pragma unroll
                for (int jp = 0; jp < 4; jp++)
                    acc[i][jp] = fma2(ad, bp[jp], acc[i][jp]);
            }
        }
    }

    const int o0 = tx << 3;
    float* part = g_aff + (size_t)kc * (1024 * 1024);
#pragma unroll
    for (int i = 0; i < 8; i++) {
        const int nn = n0 + (ty << 3) + i;
        float v[8];
#pragma unroll
        for (int jp = 0; jp < 4; jp++)
            unpack2(acc[i][jp], v[2 * jp], v[2 * jp + 1]);
        float4* dst = (float4*)(part + (size_t)nn * 1024 + (g << 6) + o0);
        dst[0] = make_float4(v[0], v[1], v[2], v[3]);
        dst[1] = make_float4(v[4], v[5], v[6], v[7]);
    }
}

// ---------------------------------------------------------------------------
// K5: reduce split-K partials + bias -> out
// ---------------------------------------------------------------------------
__global__ __launch_bounds__(256) void k5_reduce(float* __restrict__ out,
                                                 const float* __restrict__ obias)
{
    const int idx = (blockIdx.x << 8) + threadIdx.x;
    const size_t off = (size_t)idx << 2;
    float4 a = *(const float4*)(g_aff + off);
    float4 b = *(const float4*)(g_aff + off + (1u << 20));
    float4 c = *(const float4*)(g_aff + off + (2u << 20));
    float4 d = *(const float4*)(g_aff + off + (3u << 20));
    const float4 bb = *(const float4*)&obias[off & 1023];
    float4 r;
    r.x = a.x + b.x + c.x + d.x + bb.x;
    r.y = a.y + b.y + c.y + d.y + bb.y;
    r.z = a.z + b.z + c.z + d.z + bb.z;
    r.w = a.w + b.w + c.w + d.w + bb.w;
    *(float4*)(out + off) = r;
}

// ---------------------------------------------------------------------------
extern "C" void kernel_launch(void* const* d_in, const int* in_sizes, int n_in,
                              void* d_out, int out_size)
{
    const float* roi = (const float*)d_in[0];
    const float* pe  = (const float*)d_in[1];
    int ix = 2;
    if (ix < n_in && in_sizes[ix] == 1) ix++;
    const float* pos_w = (const float*)d_in[ix++];
    const float* pos_b = (const float*)d_in[ix++];
    const float* q_w   = (const float*)d_in[ix++];
    const float* q_b   = (const float*)d_in[ix++];
    const float* k_w   = (const float*)d_in[ix++];
    const float* k_b   = (const float*)d_in[ix++];
    const float* out_w = (const float*)d_in[ix++];
    const float* out_b = (const float*)d_in[ix++];
    float* out = (float*)d_out;

    cudaFuncSetAttribute(k1_mma, cudaFuncAttributeMaxDynamicSharedMemorySize,
                         K1_DSMEM);

    k0_convert<<<4096,            256>>>(roi, q_w, k_w, out_w);
    k1_mma    <<<dim3(24, 8),     256, K1_DSMEM>>>(q_b, k_b);
    k2_aff    <<<dim3(8, 8, 16),  256>>>();
    k3_softmax<<<1024,            256>>>(pe, pos_w, pos_b);
    k4_out    <<<dim3(8, 16, 4),  128>>>();
    k5_reduce <<<1024,            256>>>(out, out_b);
}

// round 5
// speedup vs baseline: 1.8421x; 1.0873x over previous
#include <cuda_runtime.h>
#include <cuda_bf16.h>
#include <cstdint>

// ---------------------------------------------------------------------------
// RelationNetwork v5.
// k0: fp32 -> bf16 hi/lo split of [roi; q_w; k_w; out_w]
// K1: mma.sync 3-term split GEMM; emits Q,K as bf16 hi/lo, P as fp32 (+bias)
// K2: mma.sync 3-term split: aff = 0.125 * Q K^T
// K3: fused pos-proj + log + add + softmax (512 thr, 2m/thr, prefetch 8)
// K4: out = soft @ P, split-K x4 (SIMT f32x2) ; K5: reduce + bias
// ---------------------------------------------------------------------------

__device__ float g_qkp [3u * 16u * 1024u * 64u];         // P in seg 2 (fp32)
__device__ float g_aff [1024u * 16u * 1024u];            // [n][g][m]; K4 scratch
__device__ float g_soft[16u * 1024u * 1024u];            // [g][n][m]
__device__ __nv_bfloat16 g_hi [4096u * 1024u];           // input hi split
__device__ __nv_bfloat16 g_lo [4096u * 1024u];           // input lo split
__device__ __nv_bfloat16 g_qkh[2u * 16u * 1024u * 64u];  // Q,K hi  [seg][g][n][64]
__device__ __nv_bfloat16 g_qkl[2u * 16u * 1024u * 64u];  // Q,K lo

// ---- packed f32x2 helpers ---------------------------------------------------
__device__ __forceinline__ unsigned long long pack2(float a, float b) {
    unsigned long long r;
    asm("mov.b64 %0, {%1, %2};" : "=l"(r)
        : "r"(__float_as_uint(a)), "r"(__float_as_uint(b)));
    return r;
}
__device__ __forceinline__ void unpack2(unsigned long long v, float& a, float& b) {
    unsigned int lo, hi;
    asm("mov.b64 {%0, %1}, %2;" : "=r"(lo), "=r"(hi) : "l"(v));
    a = __uint_as_float(lo);
    b = __uint_as_float(hi);
}
__device__ __forceinline__ unsigned long long fma2(unsigned long long a,
                                                   unsigned long long b,
                                                   unsigned long long c) {
    unsigned long long d;
    asm("fma.rn.f32x2 %0, %1, %2, %3;" : "=l"(d) : "l"(a), "l"(b), "l"(c));
    return d;
}

// ---- mma.sync / cp.async helpers --------------------------------------------
__device__ __forceinline__ uint32_t smem_u32(const void* p) {
    uint32_t a;
    asm("{ .reg .u64 t; cvta.to.shared.u64 t, %1; cvt.u32.u64 %0, t; }"
        : "=r"(a) : "l"(p));
    return a;
}
#define CP16(s, g) \
    asm volatile("cp.async.cg.shared.global [%0], [%1], 16;" \
                 :: "r"(s), "l"(g) : "memory")
#define CP_COMMIT() asm volatile("cp.async.commit_group;" ::: "memory")
#define CP_WAIT(n)  asm volatile("cp.async.wait_group %0;" :: "n"(n) : "memory")
#define LDSM4(r, a) \
    asm volatile("ldmatrix.sync.aligned.m8n8.x4.shared.b16 {%0,%1,%2,%3}, [%4];" \
                 : "=r"((r)[0]), "=r"((r)[1]), "=r"((r)[2]), "=r"((r)[3]) \
                 : "r"(a))
#define MMA_BF16(d, a, b0, b1) \
    asm volatile("mma.sync.aligned.m16n8k16.row.col.f32.bf16.bf16.f32 " \
                 "{%0,%1,%2,%3}, {%4,%5,%6,%7}, {%8,%9}, {%0,%1,%2,%3};" \
                 : "+f"((d)[0]), "+f"((d)[1]), "+f"((d)[2]), "+f"((d)[3]) \
                 : "r"((a)[0]), "r"((a)[1]), "r"((a)[2]), "r"((a)[3]), \
                   "r"(b0), "r"(b1))

// 64B-row swizzle (K1 stages): 4 chunks of 16B permuted by row.
__device__ __forceinline__ uint32_t swz(int r, int c) {
    return (uint32_t)(r * 64 + (((c ^ ((r >> 1) & 3)) & 3) << 4));
}
// 128B-row SW128 swizzle (K2 tiles).
__device__ __forceinline__ uint32_t sw128(uint32_t off) {
    return off ^ ((off >> 3) & 0x70);
}

// ---------------------------------------------------------------------------
// k0: split [roi; q_w; k_w; out_w] (4 x 1024x1024 fp32) into bf16 hi + lo.
// ---------------------------------------------------------------------------
__global__ __launch_bounds__(256) void k0_convert(
    const float* __restrict__ roi, const float* __restrict__ qw,
    const float* __restrict__ kw,  const float* __restrict__ ow)
{
    const size_t e = ((size_t)blockIdx.x * 256 + threadIdx.x) * 4;
    const float* src;
    size_t off;
    if (e < (1u << 20))      { src = roi; off = e; }
    else if (e < (2u << 20)) { src = qw;  off = e - (1u << 20); }
    else if (e < (3u << 20)) { src = kw;  off = e - (2u << 20); }
    else                     { src = ow;  off = e - (3u << 20); }
    const float4 v = *(const float4*)(src + off);
    float x[4] = {v.x, v.y, v.z, v.w};
    __nv_bfloat16 h[4], l[4];
#pragma unroll
    for (int i = 0; i < 4; i++) {
        h[i] = __float2bfloat16(x[i]);
        l[i] = __float2bfloat16(x[i] - __bfloat162float(h[i]));
    }
    ((__nv_bfloat162*)(g_hi + e))[0] = __nv_bfloat162(h[0], h[1]);
    ((__nv_bfloat162*)(g_hi + e))[1] = __nv_bfloat162(h[2], h[3]);
    ((__nv_bfloat162*)(g_lo + e))[0] = __nv_bfloat162(l[0], l[1]);
    ((__nv_bfloat162*)(g_lo + e))[1] = __nv_bfloat162(l[2], l[3]);
}

// ---------------------------------------------------------------------------
// K1: C[1024,3072] = A[1024,1024] @ W[3072,1024]^T via mma.sync bf16 split.
// 128x128 tile, BK=32, 8 warps (2m x 4n), 2-stage cp.async.
// Q,K segments -> bf16 hi/lo out; P segment -> fp32 out.
// ---------------------------------------------------------------------------
#define K1_STAGE 32768
#define K1_DSMEM (2 * K1_STAGE)

__device__ __forceinline__ void k1_issue(uint32_t so, int row0, int col0,
                                         int kc, int tid)
{
#pragma unroll
    for (int j = 0; j < 2; j++) {
        const int id = tid + (j << 8);
        const int r = id >> 2, c = id & 3;
        const uint32_t s = so + swz(r, c);
        const size_t goA = (size_t)(row0 + r) * 1024 + (kc << 5) + (c << 3);
        const size_t goB = (size_t)(1024 + col0 + r) * 1024 + (kc << 5) + (c << 3);
        CP16(s,         g_hi + goA);
        CP16(s +  8192, g_lo + goA);
        CP16(s + 16384, g_hi + goB);
        CP16(s + 24576, g_lo + goB);
    }
    CP_COMMIT();
}

__device__ __forceinline__ void k1_compute(uint32_t so, float acc[4][4][4],
                                           int wm, int wn, int lane)
{
    const int arow = lane & 15;
    const int achk = lane >> 4;
#pragma unroll
    for (int ks = 0; ks < 2; ks++) {
        uint32_t ah[4][4], al[4][4], bh[2][4], bl[2][4];
#pragma unroll
        for (int mi = 0; mi < 4; mi++) {
            const int r = wm * 64 + mi * 16 + arow;
            const uint32_t addr = so + swz(r, ks * 2 + achk);
            LDSM4(ah[mi], addr);
            LDSM4(al[mi], addr + 8192);
        }
#pragma unroll
        for (int nj = 0; nj < 2; nj++) {
            const int r = wn * 32 + nj * 16 + arow;
            const uint32_t addr = so + 16384 + swz(r, ks * 2 + achk);
            LDSM4(bh[nj], addr);
            LDSM4(bl[nj], addr + 8192);
        }
#pragma unroll
        for (int mi = 0; mi < 4; mi++)
#pragma unroll
            for (int n = 0; n < 4; n++) {
                const int nj = n >> 1, sb = n & 1;
                MMA_BF16(acc[mi][n], ah[mi], bh[nj][sb], bh[nj][sb + 2]);
                MMA_BF16(acc[mi][n], ah[mi], bl[nj][sb], bl[nj][sb + 2]);
                MMA_BF16(acc[mi][n], al[mi], bh[nj][sb], bh[nj][sb + 2]);
            }
    }
}

__global__ __launch_bounds__(256, 1) void k1_mma(
    const float* __restrict__ qb, const float* __restrict__ kb)
{
    extern __shared__ char sm1[];
    __shared__ float sbias[128];
    const uint32_t sbase = smem_u32(sm1);
    const int tid = threadIdx.x, lane = tid & 31, wid = tid >> 5;
    const int wm = wid >> 2, wn = wid & 3;
    const int col0 = blockIdx.x << 7, row0 = blockIdx.y << 7;
    const int seg = col0 >> 10, jb0 = col0 & 1023;

    if (tid < 128)
        sbias[tid] = (seg == 0) ? qb[jb0 + tid]
                   : ((seg == 1) ? kb[jb0 + tid] : 0.0f);

    float acc[4][4][4];
#pragma unroll
    for (int i = 0; i < 4; i++)
#pragma unroll
        for (int j = 0; j < 4; j++)
#pragma unroll
            for (int q = 0; q < 4; q++) acc[i][j][q] = 0.0f;

    k1_issue(sbase, row0, col0, 0, tid);

#pragma unroll 1
    for (int kc = 0; kc < 32; kc++) {
        const uint32_t so = sbase + ((kc & 1) ? (uint32_t)K1_STAGE : 0u);
        if (kc < 31) {
            k1_issue(sbase + (((kc + 1) & 1) ? (uint32_t)K1_STAGE : 0u),
                     row0, col0, kc + 1, tid);
            CP_WAIT(1);
        } else {
            CP_WAIT(0);
        }
        __syncthreads();
        k1_compute(so, acc, wm, wn, lane);
        __syncthreads();
    }

#pragma unroll
    for (int mi = 0; mi < 4; mi++) {
        const int r0 = row0 + wm * 64 + mi * 16 + (lane >> 2);
#pragma unroll
        for (int n = 0; n < 4; n++) {
            const int lc = wn * 32 + n * 8 + ((lane & 3) << 1);
            const int jl = jb0 + lc;
            const int g = jl >> 6, d0 = jl & 63;
            const float b0 = sbias[lc], b1 = sbias[lc + 1];
            const float f00 = acc[mi][n][0] + b0, f01 = acc[mi][n][1] + b1;
            const float f10 = acc[mi][n][2] + b0, f11 = acc[mi][n][3] + b1;
            if (seg < 2) {
                const size_t bi = ((size_t)(seg * 16 + g) * 1024) * 64 + d0;
                __nv_bfloat16 h00 = __float2bfloat16(f00);
                __nv_bfloat16 h01 = __float2bfloat16(f01);
                __nv_bfloat16 h10 = __float2bfloat16(f10);
                __nv_bfloat16 h11 = __float2bfloat16(f11);
                *(__nv_bfloat162*)(g_qkh + bi + (size_t)r0 * 64) =
                    __nv_bfloat162(h00, h01);
                *(__nv_bfloat162*)(g_qkh + bi + (size_t)(r0 + 8) * 64) =
                    __nv_bfloat162(h10, h11);
                *(__nv_bfloat162*)(g_qkl + bi + (size_t)r0 * 64) =
                    __nv_bfloat162(
                        __float2bfloat16(f00 - __bfloat162float(h00)),
                        __float2bfloat16(f01 - __bfloat162float(h01)));
                *(__nv_bfloat162*)(g_qkl + bi + (size_t)(r0 + 8) * 64) =
                    __nv_bfloat162(
                        __float2bfloat16(f10 - __bfloat162float(h10)),
                        __float2bfloat16(f11 - __bfloat162float(h11)));
            } else {
                float* base = g_qkp + (size_t)2 * 1048576 +
                              (size_t)g * 65536 + d0;
                *(float2*)(base + (size_t)r0 * 64) = make_float2(f00, f01);
                *(float2*)(base + (size_t)(r0 + 8) * 64) = make_float2(f10, f11);
            }
        }
    }
}

// ---------------------------------------------------------------------------
// K2: aff[n][g][m] = 0.125 * Q_g K_g^T via mma.sync bf16 split.
// Per block: one g, 128 n x 128 m, K=64 single pass. 64KB dynamic smem:
// Qh[0] Ql[16K] Kh[32K] Kl[48K], rows of 128B, SW128.
// 8 warps (2m x 4n) -> warp tile 64 n x 32 m.
// ---------------------------------------------------------------------------
#define K2_DSMEM 65536

__global__ __launch_bounds__(256, 1) void k2_mma()
{
    extern __shared__ char sm2[];
    const uint32_t sbase = smem_u32(sm2);
    const int tid = threadIdx.x, lane = tid & 31, wid = tid >> 5;
    const int wm = wid >> 2, wn = wid & 3;
    const int m0 = blockIdx.x << 7, n0 = blockIdx.y << 7, g = blockIdx.z;

    const __nv_bfloat16* srcs[4] = {
        g_qkh + ((size_t)g * 1024 + n0) * 64,
        g_qkl + ((size_t)g * 1024 + n0) * 64,
        g_qkh + ((size_t)(16 + g) * 1024 + m0) * 64,
        g_qkl + ((size_t)(16 + g) * 1024 + m0) * 64
    };
#pragma unroll
    for (int i = 0; i < 16; i++) {
        const int idx = tid + (i << 8);
        const int buf = idx >> 10, j = idx & 1023;
        const int r = j >> 3, c = j & 7;
        CP16(sbase + buf * 16384 + sw128((r << 7) + (c << 4)),
             srcs[buf] + (size_t)r * 64 + (c << 3));
    }
    CP_COMMIT();
    CP_WAIT(0);
    __syncthreads();

    float acc[4][4][4];
#pragma unroll
    for (int i = 0; i < 4; i++)
#pragma unroll
        for (int j = 0; j < 4; j++)
#pragma unroll
            for (int q = 0; q < 4; q++) acc[i][j][q] = 0.0f;

    const int arow = lane & 15, achk = lane >> 4;
#pragma unroll
    for (int ks = 0; ks < 4; ks++) {
        uint32_t ah[4][4], al[4][4], bh[2][4], bl[2][4];
#pragma unroll
        for (int mi = 0; mi < 4; mi++) {
            const int r = wm * 64 + mi * 16 + arow;
            const uint32_t addr =
                sbase + sw128((r << 7) + (ks << 5) + (achk << 4));
            LDSM4(ah[mi], addr);
            LDSM4(al[mi], addr + 16384);
        }
#pragma unroll
        for (int nj = 0; nj < 2; nj++) {
            const int r = wn * 32 + nj * 16 + arow;
            const uint32_t addr =
                sbase + 32768 + sw128((r << 7) + (ks << 5) + (achk << 4));
            LDSM4(bh[nj], addr);
            LDSM4(bl[nj], addr + 16384);
        }
#pragma unroll
        for (int mi = 0; mi < 4; mi++)
#pragma unroll
            for (int n = 0; n < 4; n++) {
                const int nj = n >> 1, sb = n & 1;
                MMA_BF16(acc[mi][n], ah[mi], bh[nj][sb], bh[nj][sb + 2]);
                MMA_BF16(acc[mi][n], ah[mi], bl[nj][sb], bl[nj][sb + 2]);
                MMA_BF16(acc[mi][n], al[mi], bh[nj][sb], bh[nj][sb + 2]);
            }
    }

#pragma unroll
    for (int mi = 0; mi < 4; mi++) {
        const int r0 = n0 + wm * 64 + mi * 16 + (lane >> 2);
#pragma unroll
        for (int n = 0; n < 4; n++) {
            const int mc = m0 + wn * 32 + n * 8 + ((lane & 3) << 1);
            *(float2*)(g_aff + ((size_t)r0 * 16 + g) * 1024 + mc) =
                make_float2(acc[mi][n][0] * 0.125f, acc[mi][n][1] * 0.125f);
            *(float2*)(g_aff + ((size_t)(r0 + 8) * 16 + g) * 1024 + mc) =
                make_float2(acc[mi][n][2] * 0.125f, acc[mi][n][3] * 0.125f);
        }
    }
}

// ---------------------------------------------------------------------------
// K3: fused position projection + relu + log + add-aff + softmax.
// 512 threads, 2 m per thread, prefetch depth 8.
// ---------------------------------------------------------------------------
__global__ __launch_bounds__(512) void k3_softmax(
    const float* __restrict__ pe,    // [64][1024 n][1024 m]
    const float* __restrict__ pw,    // [16][64]
    const float* __restrict__ pb)    // [16]
{
    __shared__ unsigned long long swd[16 * 64];
    __shared__ float sb[16];
    __shared__ float red[16][16];
    const int n = blockIdx.x;
    const int t = threadIdx.x;

    for (int idx = t; idx < 1024; idx += 512) {
        const float w = pw[idx];
        swd[idx] = pack2(w, w);
    }
    if (t < 16) sb[t] = pb[t];
    __syncthreads();

    const int m0 = t << 1;
    unsigned long long acc[16];
#pragma unroll
    for (int gg = 0; gg < 16; gg++) acc[gg] = 0ULL;

    const float* base = pe + (size_t)n * 1024 + m0;
    unsigned long long cur[8];
#pragma unroll
    for (int j = 0; j < 8; j++)
        cur[j] = __ldg((const unsigned long long*)(base + (size_t)j * 1048576));

#pragma unroll 1
    for (int e0 = 0; e0 < 64; e0 += 8) {
        unsigned long long nxt[8];
        const int eb = (e0 + 8) & 63;   // wrap: final reload hits L2
#pragma unroll
        for (int j = 0; j < 8; j++)
            nxt[j] = __ldg((const unsigned long long*)
                           (base + (size_t)(eb + j) * 1048576));
#pragma unroll
        for (int j = 0; j < 8; j++)
#pragma unroll
            for (int gg = 0; gg < 16; gg++)
                acc[gg] = fma2(swd[(gg << 6) + e0 + j], cur[j], acc[gg]);
#pragma unroll
        for (int j = 0; j < 8; j++) cur[j] = nxt[j];
    }

    float wv[16][2];
    float mx[16];
#pragma unroll
    for (int gg = 0; gg < 16; gg++) {
        float x0, x1;
        unpack2(acc[gg], x0, x1);
        const float bgg = sb[gg];
        const float2 av =
            *(const float2*)(g_aff + ((size_t)n * 16 + gg) * 1024 + m0);
        wv[gg][0] = __logf(fmaxf(x0 + bgg, 1e-6f)) + av.x;
        wv[gg][1] = __logf(fmaxf(x1 + bgg, 1e-6f)) + av.y;
        mx[gg] = fmaxf(wv[gg][0], wv[gg][1]);
    }

    const int lane = t & 31, wid = t >> 5;   // 16 warps
#pragma unroll
    for (int gg = 0; gg < 16; gg++) {
        float m = mx[gg];
#pragma unroll
        for (int off = 16; off > 0; off >>= 1)
            m = fmaxf(m, __shfl_xor_sync(0xffffffffu, m, off));
        mx[gg] = m;
    }
    if (lane == 0) {
#pragma unroll
        for (int gg = 0; gg < 16; gg++) red[gg][wid] = mx[gg];
    }
    __syncthreads();
#pragma unroll
    for (int gg = 0; gg < 16; gg++) {
        float m = red[gg][0];
#pragma unroll
        for (int w = 1; w < 16; w++) m = fmaxf(m, red[gg][w]);
        mx[gg] = m;
    }
    __syncthreads();

    float sm[16];
#pragma unroll
    for (int gg = 0; gg < 16; gg++) {
        wv[gg][0] = __expf(wv[gg][0] - mx[gg]);
        wv[gg][1] = __expf(wv[gg][1] - mx[gg]);
        float s = wv[gg][0] + wv[gg][1];
#pragma unroll
        for (int off = 16; off > 0; off >>= 1)
            s += __shfl_xor_sync(0xffffffffu, s, off);
        sm[gg] = s;
    }
    if (lane == 0) {
#pragma unroll
        for (int gg = 0; gg < 16; gg++) red[gg][wid] = sm[gg];
    }
    __syncthreads();
#pragma unroll
    for (int gg = 0; gg < 16; gg++) {
        float s = red[gg][0];
#pragma unroll
        for (int w = 1; w < 16; w++) s += red[gg][w];
        const float inv = __fdividef(1.0f, s);
        *(float2*)(g_soft + ((size_t)gg * 1024 + n) * 1024 + m0) =
            make_float2(wv[gg][0] * inv, wv[gg][1] * inv);
    }
}

// ---------------------------------------------------------------------------
// K4: batched (16x) 1024x64x1024 NN GEMM, split-K x4 (SIMT f32x2).
// ---------------------------------------------------------------------------
__global__ __launch_bounds__(128) void k4_out()
{
    __shared__ float As[16][132];
    __shared__ float Bs[16][68];
    const int tid = threadIdx.x;
    const int n0  = blockIdx.x << 7;
    const int g   = blockIdx.y;
    const int kc  = blockIdx.z;
    const float* S = g_soft + (size_t)g * (1024 * 1024) + kc * 256;
    const float* P = g_qkp + (size_t)(32 + g) * 65536 + kc * 256 * 64;

    const int tx = tid & 7;
    const int ty = tid >> 3;

    unsigned long long acc[8][4];
#pragma unroll
    for (int i = 0; i < 8; i++)
#pragma unroll
        for (int j = 0; j < 4; j++) acc[i][j] = 0ULL;

#pragma unroll 1
    for (int kt = 0; kt < 256; kt += 16) {
        float4 a[4];
#pragma unroll
        for (int q = 0; q < 4; q++)
            a[q] = *(const float4*)&S[(size_t)(n0 + tid) * 1024 + kt + q * 4];
        const int r0 = tid >> 4, c0 = (tid & 15) << 2;
        float4 bA = *(const float4*)&P[(kt + r0) * 64 + c0];
        float4 bB = *(const float4*)&P[(kt + r0 + 8) * 64 + c0];
        __syncthreads();
#pragma unroll
        for (int q = 0; q < 4; q++) {
            As[q * 4 + 0][tid] = a[q].x;
            As[q * 4 + 1][tid] = a[q].y;
            As[q * 4 + 2][tid] = a[q].z;
            As[q * 4 + 3][tid] = a[q].w;
        }
        *(float4*)&Bs[r0][c0]     = bA;
        *(float4*)&Bs[r0 + 8][c0] = bB;
        __syncthreads();
#pragma unroll
        for (int kk = 0; kk < 16; kk++) {
            const float4 av0 = *(const float4*)&As[kk][ty << 3];
            const float4 av1 = *(const float4*)&As[kk][(ty << 3) + 4];
            const ulonglong2 bv0 = *(const ulonglong2*)&Bs[kk][tx << 3];
            const ulonglong2 bv1 = *(const ulonglong2*)&Bs[kk][(tx << 3) + 4];
            const float af[8] = {av0.x, av0.y, av0.z, av0.w,
                                 av1.x, av1.y, av1.z, av1.w};
            const unsigned long long bp[4] = {bv0.x, bv0.y, bv1.x, bv1.y};
#pragma unroll
            for (int i = 0; i < 8; i++) {
                const unsigned long long ad = pack2(af[i], af[i]);
#pragma unroll
                for (int jp = 0; jp < 4; jp++)
                    acc[i][jp] = fma2(ad, bp[jp], acc[i][jp]);
            }
        }
    }

    const int o0 = tx << 3;
    float* part = g_aff + (size_t)kc * (1024 * 1024);
#pragma unroll
    for (int i = 0; i < 8; i++) {
        const int nn = n0 + (ty << 3) + i;
        float v[8];
#pragma unroll
        for (int jp = 0; jp < 4; jp++)
            unpack2(acc[i][jp], v[2 * jp], v[2 * jp + 1]);
        float4* dst = (float4*)(part + (size_t)nn * 1024 + (g << 6) + o0);
        dst[0] = make_float4(v[0], v[1], v[2], v[3]);
        dst[1] = make_float4(v[4], v[5], v[6], v[7]);
    }
}

// ---------------------------------------------------------------------------
// K5: reduce split-K partials + bias -> out
// ---------------------------------------------------------------------------
__global__ __launch_bounds__(256) void k5_reduce(float* __restrict__ out,
                                                 const float* __restrict__ obias)
{
    const int idx = (blockIdx.x << 8) + threadIdx.x;
    const size_t off = (size_t)idx << 2;
    float4 a = *(const float4*)(g_aff + off);
    float4 b = *(const float4*)(g_aff + off + (1u << 20));
    float4 c = *(const float4*)(g_aff + off + (2u << 20));
    float4 d = *(const float4*)(g_aff + off + (3u << 20));
    const float4 bb = *(const float4*)&obias[off & 1023];
    float4 r;
    r.x = a.x + b.x + c.x + d.x + bb.x;
    r.y = a.y + b.y + c.y + d.y + bb.y;
    r.z = a.z + b.z + c.z + d.z + bb.z;
    r.w = a.w + b.w + c.w + d.w + bb.w;
    *(float4*)(out + off) = r;
}

// ---------------------------------------------------------------------------
extern "C" void kernel_launch(void* const* d_in, const int* in_sizes, int n_in,
                              void* d_out, int out_size)
{
    const float* roi = (const float*)d_in[0];
    const float* pe  = (const float*)d_in[1];
    int ix = 2;
    if (ix < n_in && in_sizes[ix] == 1) ix++;
    const float* pos_w = (const float*)d_in[ix++];
    const float* pos_b = (const float*)d_in[ix++];
    const float* q_w   = (const float*)d_in[ix++];
    const float* q_b   = (const float*)d_in[ix++];
    const float* k_w   = (const float*)d_in[ix++];
    const float* k_b   = (const float*)d_in[ix++];
    const float* out_w = (const float*)d_in[ix++];
    const float* out_b = (const float*)d_in[ix++];
    float* out = (float*)d_out;

    cudaFuncSetAttribute(k1_mma, cudaFuncAttributeMaxDynamicSharedMemorySize,
                         K1_DSMEM);
    cudaFuncSetAttribute(k2_mma, cudaFuncAttributeMaxDynamicSharedMemorySize,
                         K2_DSMEM);

    k0_convert<<<4096,            256>>>(roi, q_w, k_w, out_w);
    k1_mma    <<<dim3(24, 8),     256, K1_DSMEM>>>(q_b, k_b);
    k2_mma    <<<dim3(8, 8, 16),  256, K2_DSMEM>>>();
    k3_softmax<<<1024,            512>>>(pe, pos_w, pos_b);
    k4_out    <<<dim3(8, 16, 4),  128>>>();
    k5_reduce <<<1024,            256>>>(out, out_b);
}

// round 6
// speedup vs baseline: 2.2890x; 1.2426x over previous
#include <cuda_runtime.h>
#include <cuda_bf16.h>
#include <cstdint>

// ---------------------------------------------------------------------------
// RelationNetwork v6.
// k0: fp32 -> bf16 hi/lo split of [roi; q_w; k_w; out_w]
// K1: mma.sync 3-term split GEMM; Q,K -> bf16 hi/lo [g][n][d];
//     P -> transposed bf16 hi/lo [g][o][k] (smem transpose epilogue)
// K2: mma.sync 3-term: aff = 0.125 * Q K^T -> g_aff fp32
// K3: fused pos-proj + log + add + softmax; 256thr/4m; LDS.128 weight pairs;
//     emits soft as bf16 hi/lo [g][n][m]
// K4: out = soft @ P^T via mma.sync 3-term, k-pipelined, bias fused
// ---------------------------------------------------------------------------

__device__ float g_aff [1024u * 16u * 1024u];            // 64 MB [n][g][m]
__device__ __nv_bfloat16 g_hi [4096u * 1024u];           // input hi split
__device__ __nv_bfloat16 g_lo [4096u * 1024u];           // input lo split
__device__ __nv_bfloat16 g_qkh[2u * 16u * 1024u * 64u];  // Q,K hi [seg][g][n][64]
__device__ __nv_bfloat16 g_qkl[2u * 16u * 1024u * 64u];  // Q,K lo
__device__ __nv_bfloat16 g_ph [16u * 64u * 1024u];       // P^T hi [g][o][k]
__device__ __nv_bfloat16 g_pl [16u * 64u * 1024u];       // P^T lo
__device__ __nv_bfloat16 g_sh [16u * 1024u * 1024u];     // soft hi [g][n][m]
__device__ __nv_bfloat16 g_sl [16u * 1024u * 1024u];     // soft lo

// ---- packed f32x2 helpers ---------------------------------------------------
__device__ __forceinline__ unsigned long long pack2(float a, float b) {
    unsigned long long r;
    asm("mov.b64 %0, {%1, %2};" : "=l"(r)
        : "r"(__float_as_uint(a)), "r"(__float_as_uint(b)));
    return r;
}
__device__ __forceinline__ void unpack2(unsigned long long v, float& a, float& b) {
    unsigned int lo, hi;
    asm("mov.b64 {%0, %1}, %2;" : "=r"(lo), "=r"(hi) : "l"(v));
    a = __uint_as_float(lo);
    b = __uint_as_float(hi);
}
__device__ __forceinline__ unsigned long long fma2(unsigned long long a,
                                                   unsigned long long b,
                                                   unsigned long long c) {
    unsigned long long d;
    asm("fma.rn.f32x2 %0, %1, %2, %3;" : "=l"(d) : "l"(a), "l"(b), "l"(c));
    return d;
}

// ---- mma.sync / cp.async helpers --------------------------------------------
__device__ __forceinline__ uint32_t smem_u32(const void* p) {
    uint32_t a;
    asm("{ .reg .u64 t; cvta.to.shared.u64 t, %1; cvt.u32.u64 %0, t; }"
        : "=r"(a) : "l"(p));
    return a;
}
#define CP16(s, g) \
    asm volatile("cp.async.cg.shared.global [%0], [%1], 16;" \
                 :: "r"(s), "l"(g) : "memory")
#define CP_COMMIT() asm volatile("cp.async.commit_group;" ::: "memory")
#define CP_WAIT(n)  asm volatile("cp.async.wait_group %0;" :: "n"(n) : "memory")
#define LDSM4(r, a) \
    asm volatile("ldmatrix.sync.aligned.m8n8.x4.shared.b16 {%0,%1,%2,%3}, [%4];" \
                 : "=r"((r)[0]), "=r"((r)[1]), "=r"((r)[2]), "=r"((r)[3]) \
                 : "r"(a))
#define MMA_BF16(d, a, b0, b1) \
    asm volatile("mma.sync.aligned.m16n8k16.row.col.f32.bf16.bf16.f32 " \
                 "{%0,%1,%2,%3}, {%4,%5,%6,%7}, {%8,%9}, {%0,%1,%2,%3};" \
                 : "+f"((d)[0]), "+f"((d)[1]), "+f"((d)[2]), "+f"((d)[3]) \
                 : "r"((a)[0]), "r"((a)[1]), "r"((a)[2]), "r"((a)[3]), \
                   "r"(b0), "r"(b1))

// 64B-row swizzle: 4 chunks of 16B permuted by row pair.
__device__ __forceinline__ uint32_t swz(int r, int c) {
    return (uint32_t)(r * 64 + (((c ^ ((r >> 1) & 3)) & 3) << 4));
}
// 128B-row SW128 swizzle (K2 tiles).
__device__ __forceinline__ uint32_t sw128(uint32_t off) {
    return off ^ ((off >> 3) & 0x70);
}

// ---------------------------------------------------------------------------
// k0: split [roi; q_w; k_w; out_w] into bf16 hi + lo.
// ---------------------------------------------------------------------------
__global__ __launch_bounds__(256) void k0_convert(
    const float* __restrict__ roi, const float* __restrict__ qw,
    const float* __restrict__ kw,  const float* __restrict__ ow)
{
    const size_t e = ((size_t)blockIdx.x * 256 + threadIdx.x) * 4;
    const float* src;
    size_t off;
    if (e < (1u << 20))      { src = roi; off = e; }
    else if (e < (2u << 20)) { src = qw;  off = e - (1u << 20); }
    else if (e < (3u << 20)) { src = kw;  off = e - (2u << 20); }
    else                     { src = ow;  off = e - (3u << 20); }
    const float4 v = *(const float4*)(src + off);
    float x[4] = {v.x, v.y, v.z, v.w};
    __nv_bfloat16 h[4], l[4];
#pragma unroll
    for (int i = 0; i < 4; i++) {
        h[i] = __float2bfloat16(x[i]);
        l[i] = __float2bfloat16(x[i] - __bfloat162float(h[i]));
    }
    ((__nv_bfloat162*)(g_hi + e))[0] = __nv_bfloat162(h[0], h[1]);
    ((__nv_bfloat162*)(g_hi + e))[1] = __nv_bfloat162(h[2], h[3]);
    ((__nv_bfloat162*)(g_lo + e))[0] = __nv_bfloat162(l[0], l[1]);
    ((__nv_bfloat162*)(g_lo + e))[1] = __nv_bfloat162(l[2], l[3]);
}

// ---------------------------------------------------------------------------
// K1: C[1024,3072] = A @ W^T via mma.sync bf16 split. 128x128 tile, BK=32,
// 8 warps (2m x 4n), 2-stage cp.async. seg<2 -> bf16 hi/lo [g][n][d];
// seg==2 -> smem transpose -> bf16 hi/lo [g][o][k].
// ---------------------------------------------------------------------------
#define K1_STAGE 32768
#define K1_DSMEM 67584        // max(2 stages = 64K, transpose 128x132 f32)

__device__ __forceinline__ void k1_issue(uint32_t so, int row0, int col0,
                                         int kc, int tid)
{
#pragma unroll
    for (int j = 0; j < 2; j++) {
        const int id = tid + (j << 8);
        const int r = id >> 2, c = id & 3;
        const uint32_t s = so + swz(r, c);
        const size_t goA = (size_t)(row0 + r) * 1024 + (kc << 5) + (c << 3);
        const size_t goB = (size_t)(1024 + col0 + r) * 1024 + (kc << 5) + (c << 3);
        CP16(s,         g_hi + goA);
        CP16(s +  8192, g_lo + goA);
        CP16(s + 16384, g_hi + goB);
        CP16(s + 24576, g_lo + goB);
    }
    CP_COMMIT();
}

__device__ __forceinline__ void k1_compute(uint32_t so, float acc[4][4][4],
                                           int wm, int wn, int lane)
{
    const int arow = lane & 15;
    const int achk = lane >> 4;
#pragma unroll
    for (int ks = 0; ks < 2; ks++) {
        uint32_t ah[4][4], al[4][4], bh[2][4], bl[2][4];
#pragma unroll
        for (int mi = 0; mi < 4; mi++) {
            const int r = wm * 64 + mi * 16 + arow;
            const uint32_t addr = so + swz(r, ks * 2 + achk);
            LDSM4(ah[mi], addr);
            LDSM4(al[mi], addr + 8192);
        }
#pragma unroll
        for (int nj = 0; nj < 2; nj++) {
            const int r = wn * 32 + nj * 16 + arow;
            const uint32_t addr = so + 16384 + swz(r, ks * 2 + achk);
            LDSM4(bh[nj], addr);
            LDSM4(bl[nj], addr + 8192);
        }
#pragma unroll
        for (int mi = 0; mi < 4; mi++)
#pragma unroll
            for (int n = 0; n < 4; n++) {
                const int nj = n >> 1, sb = n & 1;
                MMA_BF16(acc[mi][n], ah[mi], bh[nj][sb], bh[nj][sb + 2]);
                MMA_BF16(acc[mi][n], ah[mi], bl[nj][sb], bl[nj][sb + 2]);
                MMA_BF16(acc[mi][n], al[mi], bh[nj][sb], bh[nj][sb + 2]);
            }
    }
}

__global__ __launch_bounds__(256, 1) void k1_mma(
    const float* __restrict__ qb, const float* __restrict__ kb)
{
    extern __shared__ char sm1[];
    __shared__ float sbias[128];
    const uint32_t sbase = smem_u32(sm1);
    const int tid = threadIdx.x, lane = tid & 31, wid = tid >> 5;
    const int wm = wid >> 2, wn = wid & 3;
    const int col0 = blockIdx.x << 7, row0 = blockIdx.y << 7;
    const int seg = col0 >> 10, jb0 = col0 & 1023;

    if (tid < 128)
        sbias[tid] = (seg == 0) ? qb[jb0 + tid]
                   : ((seg == 1) ? kb[jb0 + tid] : 0.0f);

    float acc[4][4][4];
#pragma unroll
    for (int i = 0; i < 4; i++)
#pragma unroll
        for (int j = 0; j < 4; j++)
#pragma unroll
            for (int q = 0; q < 4; q++) acc[i][j][q] = 0.0f;

    k1_issue(sbase, row0, col0, 0, tid);

#pragma unroll 1
    for (int kc = 0; kc < 32; kc++) {
        const uint32_t so = sbase + ((kc & 1) ? (uint32_t)K1_STAGE : 0u);
        if (kc < 31) {
            k1_issue(sbase + (((kc + 1) & 1) ? (uint32_t)K1_STAGE : 0u),
                     row0, col0, kc + 1, tid);
            CP_WAIT(1);
        } else {
            CP_WAIT(0);
        }
        __syncthreads();
        k1_compute(so, acc, wm, wn, lane);
        __syncthreads();
    }

    if (seg < 2) {
#pragma unroll
        for (int mi = 0; mi < 4; mi++) {
            const int r0 = row0 + wm * 64 + mi * 16 + (lane >> 2);
#pragma unroll
            for (int n = 0; n < 4; n++) {
                const int lc = wn * 32 + n * 8 + ((lane & 3) << 1);
                const int jl = jb0 + lc;
                const int g = jl >> 6, d0 = jl & 63;
                const float b0 = sbias[lc], b1 = sbias[lc + 1];
                const float f00 = acc[mi][n][0] + b0, f01 = acc[mi][n][1] + b1;
                const float f10 = acc[mi][n][2] + b0, f11 = acc[mi][n][3] + b1;
                const size_t bi = ((size_t)(seg * 16 + g) * 1024) * 64 + d0;
                __nv_bfloat16 h00 = __float2bfloat16(f00);
                __nv_bfloat16 h01 = __float2bfloat16(f01);
                __nv_bfloat16 h10 = __float2bfloat16(f10);
                __nv_bfloat16 h11 = __float2bfloat16(f11);
                *(__nv_bfloat162*)(g_qkh + bi + (size_t)r0 * 64) =
                    __nv_bfloat162(h00, h01);
                *(__nv_bfloat162*)(g_qkh + bi + (size_t)(r0 + 8) * 64) =
                    __nv_bfloat162(h10, h11);
                *(__nv_bfloat162*)(g_qkl + bi + (size_t)r0 * 64) =
                    __nv_bfloat162(
                        __float2bfloat16(f00 - __bfloat162float(h00)),
                        __float2bfloat16(f01 - __bfloat162float(h01)));
                *(__nv_bfloat162*)(g_qkl + bi + (size_t)(r0 + 8) * 64) =
                    __nv_bfloat162(
                        __float2bfloat16(f10 - __bfloat162float(h10)),
                        __float2bfloat16(f11 - __bfloat162float(h11)));
            }
        }
    } else {
        // transpose through smem: smf[col][row] with stride 132
        float* smf = (float*)sm1;
#pragma unroll
        for (int mi = 0; mi < 4; mi++) {
            const int rl = wm * 64 + mi * 16 + (lane >> 2);
#pragma unroll
            for (int n = 0; n < 4; n++) {
                const int lc = wn * 32 + n * 8 + ((lane & 3) << 1);
                smf[lc * 132 + rl]           = acc[mi][n][0];
                smf[(lc + 1) * 132 + rl]     = acc[mi][n][1];
                smf[lc * 132 + rl + 8]       = acc[mi][n][2];
                smf[(lc + 1) * 132 + rl + 8] = acc[mi][n][3];
            }
        }
        __syncthreads();
        const int c = tid >> 1, half = tid & 1;     // col 0..127, n-half
        const int jl = jb0 + c;
        const int g = jl >> 6, o = jl & 63;
        __nv_bfloat16* dh = g_ph + ((size_t)g * 64 + o) * 1024 +
                            row0 + half * 64;
        __nv_bfloat16* dl = g_pl + ((size_t)g * 64 + o) * 1024 +
                            row0 + half * 64;
        const float* srow = smf + c * 132 + half * 64;
#pragma unroll
        for (int i4 = 0; i4 < 16; i4++) {
            const float4 v = *(const float4*)(srow + i4 * 4);
            __nv_bfloat16 h0 = __float2bfloat16(v.x);
            __nv_bfloat16 h1 = __float2bfloat16(v.y);
            __nv_bfloat16 h2 = __float2bfloat16(v.z);
            __nv_bfloat16 h3 = __float2bfloat16(v.w);
            ((__nv_bfloat162*)(dh + i4 * 4))[0] = __nv_bfloat162(h0, h1);
            ((__nv_bfloat162*)(dh + i4 * 4))[1] = __nv_bfloat162(h2, h3);
            ((__nv_bfloat162*)(dl + i4 * 4))[0] = __nv_bfloat162(
                __float2bfloat16(v.x - __bfloat162float(h0)),
                __float2bfloat16(v.y - __bfloat162float(h1)));
            ((__nv_bfloat162*)(dl + i4 * 4))[1] = __nv_bfloat162(
                __float2bfloat16(v.z - __bfloat162float(h2)),
                __float2bfloat16(v.w - __bfloat162float(h3)));
        }
    }
}

// ---------------------------------------------------------------------------
// K2: aff = 0.125 * Q K^T via mma.sync split. One g per block, 128x128, K=64.
// ---------------------------------------------------------------------------
#define K2_DSMEM 65536

__global__ __launch_bounds__(256, 1) void k2_mma()
{
    extern __shared__ char sm2[];
    const uint32_t sbase = smem_u32(sm2);
    const int tid = threadIdx.x, lane = tid & 31, wid = tid >> 5;
    const int wm = wid >> 2, wn = wid & 3;
    const int m0 = blockIdx.x << 7, n0 = blockIdx.y << 7, g = blockIdx.z;

    const __nv_bfloat16* srcs[4] = {
        g_qkh + ((size_t)g * 1024 + n0) * 64,
        g_qkl + ((size_t)g * 1024 + n0) * 64,
        g_qkh + ((size_t)(16 + g) * 1024 + m0) * 64,
        g_qkl + ((size_t)(16 + g) * 1024 + m0) * 64
    };
#pragma unroll
    for (int i = 0; i < 16; i++) {
        const int idx = tid + (i << 8);
        const int buf = idx >> 10, j = idx & 1023;
        const int r = j >> 3, c = j & 7;
        CP16(sbase + buf * 16384 + sw128((r << 7) + (c << 4)),
             srcs[buf] + (size_t)r * 64 + (c << 3));
    }
    CP_COMMIT();
    CP_WAIT(0);
    __syncthreads();

    float acc[4][4][4];
#pragma unroll
    for (int i = 0; i < 4; i++)
#pragma unroll
        for (int j = 0; j < 4; j++)
#pragma unroll
            for (int q = 0; q < 4; q++) acc[i][j][q] = 0.0f;

    const int arow = lane & 15, achk = lane >> 4;
#pragma unroll
    for (int ks = 0; ks < 4; ks++) {
        uint32_t ah[4][4], al[4][4], bh[2][4], bl[2][4];
#pragma unroll
        for (int mi = 0; mi < 4; mi++) {
            const int r = wm * 64 + mi * 16 + arow;
            const uint32_t addr =
                sbase + sw128((r << 7) + (ks << 5) + (achk << 4));
            LDSM4(ah[mi], addr);
            LDSM4(al[mi], addr + 16384);
        }
#pragma unroll
        for (int nj = 0; nj < 2; nj++) {
            const int r = wn * 32 + nj * 16 + arow;
            const uint32_t addr =
                sbase + 32768 + sw128((r << 7) + (ks << 5) + (achk << 4));
            LDSM4(bh[nj], addr);
            LDSM4(bl[nj], addr + 16384);
        }
#pragma unroll
        for (int mi = 0; mi < 4; mi++)
#pragma unroll
            for (int n = 0; n < 4; n++) {
                const int nj = n >> 1, sb = n & 1;
                MMA_BF16(acc[mi][n], ah[mi], bh[nj][sb], bh[nj][sb + 2]);
                MMA_BF16(acc[mi][n], ah[mi], bl[nj][sb], bl[nj][sb + 2]);
                MMA_BF16(acc[mi][n], al[mi], bh[nj][sb], bh[nj][sb + 2]);
            }
    }

#pragma unroll
    for (int mi = 0; mi < 4; mi++) {
        const int r0 = n0 + wm * 64 + mi * 16 + (lane >> 2);
#pragma unroll
        for (int n = 0; n < 4; n++) {
            const int mc = m0 + wn * 32 + n * 8 + ((lane & 3) << 1);
            *(float2*)(g_aff + ((size_t)r0 * 16 + g) * 1024 + mc) =
                make_float2(acc[mi][n][0] * 0.125f, acc[mi][n][1] * 0.125f);
            *(float2*)(g_aff + ((size_t)(r0 + 8) * 16 + g) * 1024 + mc) =
                make_float2(acc[mi][n][2] * 0.125f, acc[mi][n][3] * 0.125f);
        }
    }
}

// ---------------------------------------------------------------------------
// K3: fused pos-proj + log + add-aff + softmax -> soft bf16 hi/lo.
// 256 threads, 4 m/thread, LDS.128 dup-pair weights (1 LDS : 4 FMA2).
// ---------------------------------------------------------------------------
__global__ __launch_bounds__(256, 2) void k3_softmax(
    const float* __restrict__ pe,    // [64][1024 n][1024 m]
    const float* __restrict__ pw,    // [16][64]
    const float* __restrict__ pb)    // [16]
{
    __shared__ ulonglong2 swd2[16][32];   // [gg][e/2] dup pairs
    __shared__ float sb[16];
    __shared__ float red[16][8];
    const int n = blockIdx.x;
    const int t = threadIdx.x;

    for (int idx = t; idx < 1024; idx += 256) {
        const float w = pw[idx];
        ((unsigned long long*)swd2)[idx] = pack2(w, w);
    }
    if (t < 16) sb[t] = pb[t];
    __syncthreads();

    const int m0 = t << 2;
    unsigned long long acc[16][2];
#pragma unroll
    for (int gg = 0; gg < 16; gg++) { acc[gg][0] = 0ULL; acc[gg][1] = 0ULL; }

    const float* base = pe + (size_t)n * 1024 + m0;
    ulonglong2 cur[4];
#pragma unroll
    for (int j = 0; j < 4; j++)
        cur[j] = __ldg((const ulonglong2*)(base + (size_t)j * 1048576));

#pragma unroll 1
    for (int e0 = 0; e0 < 64; e0 += 4) {
        ulonglong2 nxt[4];
        const int eb = (e0 + 4) & 63;   // wrap: final reload hits L2
#pragma unroll
        for (int j = 0; j < 4; j++)
            nxt[j] = __ldg((const ulonglong2*)
                           (base + (size_t)(eb + j) * 1048576));
#pragma unroll
        for (int j = 0; j < 4; j += 2) {
            const ulonglong2 c0 = cur[j], c1 = cur[j + 1];
            const int ep = (e0 + j) >> 1;
#pragma unroll
            for (int gg = 0; gg < 16; gg++) {
                const ulonglong2 w = swd2[gg][ep];
                acc[gg][0] = fma2(w.x, c0.x, acc[gg][0]);
                acc[gg][0] = fma2(w.y, c1.x, acc[gg][0]);
                acc[gg][1] = fma2(w.x, c0.y, acc[gg][1]);
                acc[gg][1] = fma2(w.y, c1.y, acc[gg][1]);
            }
        }
#pragma unroll
        for (int j = 0; j < 4; j++) cur[j] = nxt[j];
    }

    float wv[16][4];
    float mx[16];
#pragma unroll
    for (int gg = 0; gg < 16; gg++) {
        float x0, x1, x2, x3;
        unpack2(acc[gg][0], x0, x1);
        unpack2(acc[gg][1], x2, x3);
        const float bgg = sb[gg];
        const float4 av =
            *(const float4*)(g_aff + ((size_t)n * 16 + gg) * 1024 + m0);
        wv[gg][0] = __logf(fmaxf(x0 + bgg, 1e-6f)) + av.x;
        wv[gg][1] = __logf(fmaxf(x1 + bgg, 1e-6f)) + av.y;
        wv[gg][2] = __logf(fmaxf(x2 + bgg, 1e-6f)) + av.z;
        wv[gg][3] = __logf(fmaxf(x3 + bgg, 1e-6f)) + av.w;
        mx[gg] = fmaxf(fmaxf(wv[gg][0], wv[gg][1]),
                       fmaxf(wv[gg][2], wv[gg][3]));
    }

    const int lane = t & 31, wid = t >> 5;
#pragma unroll
    for (int gg = 0; gg < 16; gg++) {
        float m = mx[gg];
#pragma unroll
        for (int off = 16; off > 0; off >>= 1)
            m = fmaxf(m, __shfl_xor_sync(0xffffffffu, m, off));
        mx[gg] = m;
    }
    if (lane == 0) {
#pragma unroll
        for (int gg = 0; gg < 16; gg++) red[gg][wid] = mx[gg];
    }
    __syncthreads();
#pragma unroll
    for (int gg = 0; gg < 16; gg++) {
        float m = red[gg][0];
#pragma unroll
        for (int w = 1; w < 8; w++) m = fmaxf(m, red[gg][w]);
        mx[gg] = m;
    }
    __syncthreads();

    float sm[16];
#pragma unroll
    for (int gg = 0; gg < 16; gg++) {
        float s = 0.0f;
#pragma unroll
        for (int j = 0; j < 4; j++) {
            wv[gg][j] = __expf(wv[gg][j] - mx[gg]);
            s += wv[gg][j];
        }
#pragma unroll
        for (int off = 16; off > 0; off >>= 1)
            s += __shfl_xor_sync(0xffffffffu, s, off);
        sm[gg] = s;
    }
    if (lane == 0) {
#pragma unroll
        for (int gg = 0; gg < 16; gg++) red[gg][wid] = sm[gg];
    }
    __syncthreads();
#pragma unroll
    for (int gg = 0; gg < 16; gg++) {
        float s = red[gg][0];
#pragma unroll
        for (int w = 1; w < 8; w++) s += red[gg][w];
        const float inv = __fdividef(1.0f, s);
        const float v0 = wv[gg][0] * inv, v1 = wv[gg][1] * inv;
        const float v2 = wv[gg][2] * inv, v3 = wv[gg][3] * inv;
        const __nv_bfloat16 h0 = __float2bfloat16(v0);
        const __nv_bfloat16 h1 = __float2bfloat16(v1);
        const __nv_bfloat16 h2 = __float2bfloat16(v2);
        const __nv_bfloat16 h3 = __float2bfloat16(v3);
        const size_t so = ((size_t)gg * 1024 + n) * 1024 + m0;
        ((__nv_bfloat162*)(g_sh + so))[0] = __nv_bfloat162(h0, h1);
        ((__nv_bfloat162*)(g_sh + so))[1] = __nv_bfloat162(h2, h3);
        ((__nv_bfloat162*)(g_sl + so))[0] = __nv_bfloat162(
            __float2bfloat16(v0 - __bfloat162float(h0)),
            __float2bfloat16(v1 - __bfloat162float(h1)));
        ((__nv_bfloat162*)(g_sl + so))[1] = __nv_bfloat162(
            __float2bfloat16(v2 - __bfloat162float(h2)),
            __float2bfloat16(v3 - __bfloat162float(h3)));
    }
}

// ---------------------------------------------------------------------------
// K4: out[n][g*64+o] = sum_k soft[g][n][k] * P^T[g][o][k] + out_b.
// mma.sync 3-term split; 128n x 64o block, BK=32, 2-stage cp.async.
// 8 warps (2m x 4n) -> warp tile 64n x 16o. Grid (8 n-tiles, 16 g).
// Stage: Ah 8K | Al 8K | Bh 4K | Bl 4K = 24K; 2 stages.
// ---------------------------------------------------------------------------
#define K4_STAGE 24576
#define K4_DSMEM (2 * K4_STAGE)

__device__ __forceinline__ void k4_issue(uint32_t so, int n0, int g,
                                         int kt, int tid)
{
#pragma unroll
    for (int j = 0; j < 2; j++) {
        const int id = tid + (j << 8);
        const int r = id >> 2, c = id & 3;
        const uint32_t s = so + swz(r, c);
        const size_t ga = ((size_t)g * 1024 + n0 + r) * 1024 + kt + (c << 3);
        CP16(s,        g_sh + ga);
        CP16(s + 8192, g_sl + ga);
    }
    {
        const int r = tid >> 2, c = tid & 3;
        const uint32_t s = so + 16384 + swz(r, c);
        const size_t gb = ((size_t)g * 64 + r) * 1024 + kt + (c << 3);
        CP16(s,        g_ph + gb);
        CP16(s + 4096, g_pl + gb);
    }
    CP_COMMIT();
}

__global__ __launch_bounds__(256, 1) void k4_mma(float* __restrict__ out,
                                                 const float* __restrict__ obias)
{
    extern __shared__ char sm4[];
    __shared__ float sbias[64];
    const uint32_t sbase = smem_u32(sm4);
    const int tid = threadIdx.x, lane = tid & 31, wid = tid >> 5;
    const int wm = wid >> 2, wn = wid & 3;
    const int n0 = blockIdx.x << 7, g = blockIdx.y;

    if (tid < 64) sbias[tid] = obias[(g << 6) + tid];

    float acc[4][2][4];
#pragma unroll
    for (int i = 0; i < 4; i++)
#pragma unroll
        for (int j = 0; j < 2; j++)
#pragma unroll
            for (int q = 0; q < 4; q++) acc[i][j][q] = 0.0f;

    k4_issue(sbase, n0, g, 0, tid);

    const int arow = lane & 15, achk = lane >> 4;
#pragma unroll 1
    for (int kc = 0; kc < 32; kc++) {
        const uint32_t so = sbase + ((kc & 1) ? (uint32_t)K4_STAGE : 0u);
        if (kc < 31) {
            k4_issue(sbase + (((kc + 1) & 1) ? (uint32_t)K4_STAGE : 0u),
                     n0, g, (kc + 1) << 5, tid);
            CP_WAIT(1);
        } else {
            CP_WAIT(0);
        }
        __syncthreads();
#pragma unroll
        for (int ks = 0; ks < 2; ks++) {
            uint32_t ah[4][4], al[4][4], bh[4], bl[4];
#pragma unroll
            for (int mi = 0; mi < 4; mi++) {
                const int r = wm * 64 + mi * 16 + arow;
                const uint32_t addr = so + swz(r, ks * 2 + achk);
                LDSM4(ah[mi], addr);
                LDSM4(al[mi], addr + 8192);
            }
            {
                const int r = wn * 16 + arow;
                const uint32_t addr = so + 16384 + swz(r, ks * 2 + achk);
                LDSM4(bh, addr);
                LDSM4(bl, addr + 4096);
            }
#pragma unroll
            for (int mi = 0; mi < 4; mi++)
#pragma unroll
                for (int n = 0; n < 2; n++) {
                    MMA_BF16(acc[mi][n], ah[mi], bh[n], bh[n + 2]);
                    MMA_BF16(acc[mi][n], ah[mi], bl[n], bl[n + 2]);
                    MMA_BF16(acc[mi][n], al[mi], bh[n], bh[n + 2]);
                }
        }
        __syncthreads();
    }

#pragma unroll
    for (int mi = 0; mi < 4; mi++) {
        const int r0 = n0 + wm * 64 + mi * 16 + (lane >> 2);
#pragma unroll
        for (int n = 0; n < 2; n++) {
            const int lc = wn * 16 + n * 8 + ((lane & 3) << 1);
            const float b0 = sbias[lc], b1 = sbias[lc + 1];
            float* dst = out + (size_t)r0 * 1024 + (g << 6) + lc;
            dst[0] = acc[mi][n][0] + b0;
            dst[1] = acc[mi][n][1] + b1;
            dst[1024 * 8 + 0] = acc[mi][n][2] + b0;
            dst[1024 * 8 + 1] = acc[mi][n][3] + b1;
        }
    }
}

// ---------------------------------------------------------------------------
extern "C" void kernel_launch(void* const* d_in, const int* in_sizes, int n_in,
                              void* d_out, int out_size)
{
    const float* roi = (const float*)d_in[0];
    const float* pe  = (const float*)d_in[1];
    int ix = 2;
    if (ix < n_in && in_sizes[ix] == 1) ix++;
    const float* pos_w = (const float*)d_in[ix++];
    const float* pos_b = (const float*)d_in[ix++];
    const float* q_w   = (const float*)d_in[ix++];
    const float* q_b   = (const float*)d_in[ix++];
    const float* k_w   = (const float*)d_in[ix++];
    const float* k_b   = (const float*)d_in[ix++];
    const float* out_w = (const float*)d_in[ix++];
    const float* out_b = (const float*)d_in[ix++];
    float* out = (float*)d_out;

    cudaFuncSetAttribute(k1_mma, cudaFuncAttributeMaxDynamicSharedMemorySize,
                         K1_DSMEM);
    cudaFuncSetAttribute(k2_mma, cudaFuncAttributeMaxDynamicSharedMemorySize,
                         K2_DSMEM);
    cudaFuncSetAttribute(k4_mma, cudaFuncAttributeMaxDynamicSharedMemorySize,
                         K4_DSMEM);

    k0_convert<<<4096,            256>>>(roi, q_w, k_w, out_w);
    k1_mma    <<<dim3(24, 8),     256, K1_DSMEM>>>(q_b, k_b);
    k2_mma    <<<dim3(8, 8, 16),  256, K2_DSMEM>>>();
    k3_softmax<<<1024,            256>>>(pe, pos_w, pos_b);
    k4_mma    <<<dim3(8, 16),     256, K4_DSMEM>>>(out, out_b);
}